// round 13
// baseline (speedup 1.0000x reference)
#include <cuda_runtime.h>
#include <cuda_fp16.h>
#include <stdint.h>
#include <math.h>

#define B_   2
#define S_   2048
#define D_   1024
#define H_   16
#define DH_  64
#define NT_  (B_ * S_)          // 4096 tokens

// Scratch (allocation-free rule -> __device__ globals)
__device__ __half g_qh[NT_ * D_];
__device__ __half g_kh[NT_ * D_];
__device__ __half g_vh[NT_ * D_];
__device__ __half g_atth[NT_ * D_];
__device__ __half g_xh[NT_ * D_];
__device__ __half g_wqh[D_ * D_];
__device__ __half g_wkh[D_ * D_];
__device__ __half g_wvh[D_ * D_];
__device__ __half g_woh[D_ * D_];

__device__ __forceinline__ void mma16816(float* c, const uint32_t* a,
                                         uint32_t b0, uint32_t b1)
{
    asm volatile(
        "mma.sync.aligned.m16n8k16.row.col.f32.f16.f16.f32 "
        "{%0,%1,%2,%3}, {%4,%5,%6,%7}, {%8,%9}, {%0,%1,%2,%3};\n"
        : "+f"(c[0]), "+f"(c[1]), "+f"(c[2]), "+f"(c[3])
        : "r"(a[0]), "r"(a[1]), "r"(a[2]), "r"(a[3]), "r"(b0), "r"(b1));
}

__device__ __forceinline__ void ldsm4(uint32_t* r, const void* p)
{
    uint32_t a = (uint32_t)__cvta_generic_to_shared(p);
    asm volatile("ldmatrix.sync.aligned.m8n8.x4.shared.b16 {%0,%1,%2,%3}, [%4];"
                 : "=r"(r[0]), "=r"(r[1]), "=r"(r[2]), "=r"(r[3]) : "r"(a));
}

__device__ __forceinline__ void cp16(void* smem, const void* gmem)
{
    uint32_t sa = (uint32_t)__cvta_generic_to_shared(smem);
    asm volatile("cp.async.cg.shared.global [%0], [%1], 16;\n"
                 :: "r"(sa), "l"(gmem));
}
__device__ __forceinline__ void cp_commit()
{
    asm volatile("cp.async.commit_group;\n");
}

// ---------------------------------------------------------------------------
// Fused fp32 -> fp16 convert for x + 4 weights (8M elements total).
// ---------------------------------------------------------------------------
__global__ __launch_bounds__(256) void convert_all_kernel(
    const float* __restrict__ x,  const float* __restrict__ wq,
    const float* __restrict__ wk, const float* __restrict__ wv,
    const float* __restrict__ wo,
    __half* __restrict__ xh, __half* __restrict__ wqh,
    __half* __restrict__ wkh, __half* __restrict__ wvh,
    __half* __restrict__ woh)
{
    size_t gi = ((size_t)blockIdx.x * 256 + threadIdx.x) * 16;
    int seg = (int)(gi >> 20);
    const float* in; __half* out; size_t off;
    if (seg < 4)      { in = x;  out = xh;  off = gi; }
    else if (seg == 4){ in = wq; out = wqh; off = gi - (4u << 20); }
    else if (seg == 5){ in = wk; out = wkh; off = gi - (5u << 20); }
    else if (seg == 6){ in = wv; out = wvh; off = gi - (6u << 20); }
    else              { in = wo; out = woh; off = gi - (7u << 20); }

    float4 v0 = *(const float4*)&in[off];
    float4 v1 = *(const float4*)&in[off + 4];
    float4 v2 = *(const float4*)&in[off + 8];
    float4 v3 = *(const float4*)&in[off + 12];
    __half2 h[8];
    h[0] = __floats2half2_rn(v0.x, v0.y); h[1] = __floats2half2_rn(v0.z, v0.w);
    h[2] = __floats2half2_rn(v1.x, v1.y); h[3] = __floats2half2_rn(v1.z, v1.w);
    h[4] = __floats2half2_rn(v2.x, v2.y); h[5] = __floats2half2_rn(v2.z, v2.w);
    h[6] = __floats2half2_rn(v3.x, v3.y); h[7] = __floats2half2_rn(v3.z, v3.w);
    *(int4*)&out[off]     = *(int4*)&h[0];
    *(int4*)&out[off + 8] = *(int4*)&h[4];
}

// ---------------------------------------------------------------------------
// C[M,N] = A[M,K] @ W[N,K]^T  fp16 mma, f32 accum, OutT epilogue.
// Block 128x128, BK=64, 8 warps (2x4), warp tile 64x32 (4x4 mma grid).
// 3-stage cp.async ring, ONE syncthreads per slab, ldmatrix fragments.
// blockIdx.z picks W/C pair (QKV fuse).
// ---------------------------------------------------------------------------
#define LDG3 72                      // pitch in halves (144 B)
#define GT3  (128 * LDG3)            // halves per operand tile
#define GSM3 (3 * 2 * GT3 * 2)       // bytes: 3 stages x (A+B) x 2B = 110592

template <typename OutT>
__global__ __launch_bounds__(256, 2) void gemm_nt_f16_kernel(
    const __half* __restrict__ A,
    const __half* __restrict__ W0, const __half* __restrict__ W1,
    const __half* __restrict__ W2,
    OutT* __restrict__ C0, OutT* __restrict__ C1, OutT* __restrict__ C2,
    int M, int N, int K)
{
    extern __shared__ __half smem[];
    // layout: [stage][A tile GT3][B tile GT3]
    const __half* W = (blockIdx.z == 0) ? W0 : (blockIdx.z == 1) ? W1 : W2;
    OutT*         C = (blockIdx.z == 0) ? C0 : (blockIdx.z == 1) ? C1 : C2;

    int tid  = threadIdx.x;
    int wid  = tid >> 5, lane = tid & 31;
    int gid  = lane >> 2, tig = lane & 3;
    int wm   = (wid & 1) * 64;
    int wn   = (wid >> 1) * 32;
    int m0   = blockIdx.y * 128;
    int n0   = blockIdx.x * 128;

    // ldmatrix per-lane base offsets (halves)
    int aoff = (wm + (lane & 15)) * LDG3 + (lane >> 4) * 8;
    int boff = (wn + (lane & 7) + ((lane >> 4) & 1) * 8) * LDG3
             + ((lane >> 3) & 1) * 8;

    float acc[4][4][4] = {};

    const int NIT = K / 64;          // 16

    // loader: 1024 16B-chunks per operand per stage; 256 threads x 4
    auto load_stage = [&](int slot, int k0) {
        __half* as = smem + slot * 2 * GT3;
        __half* bs = as + GT3;
        #pragma unroll
        for (int u = 0; u < 4; u++) {
            int c = tid + u * 256;              // 0..1023
            int row = c >> 3, col = (c & 7) * 8;
            cp16(&as[row * LDG3 + col], &A[(size_t)(m0 + row) * K + k0 + col]);
            cp16(&bs[row * LDG3 + col], &W[(size_t)(n0 + row) * K + k0 + col]);
        }
        cp_commit();
    };

    load_stage(0, 0);
    load_stage(1, 64);

    for (int t = 0; t < NIT; t++) {
        if (t + 1 < NIT) asm volatile("cp.async.wait_group 1;\n");
        else             asm volatile("cp.async.wait_group 0;\n");
        __syncthreads();

        // prefetch stage t+2 into slot (t+2)%3 (held stage t-1; readers done)
        if (t + 2 < NIT) load_stage((t + 2) % 3, (t + 2) * 64);

        const __half* as = smem + (t % 3) * 2 * GT3;
        const __half* bs = as + GT3;

        #pragma unroll
        for (int ks = 0; ks < 4; ks++) {
            int kb = ks * 16;
            uint32_t af[4][4], bf[2][4];
            #pragma unroll
            for (int i = 0; i < 4; i++)
                ldsm4(af[i], as + aoff + i * 16 * LDG3 + kb);
            #pragma unroll
            for (int jp = 0; jp < 2; jp++)
                ldsm4(bf[jp], bs + boff + jp * 16 * LDG3 + kb);
            #pragma unroll
            for (int i = 0; i < 4; i++) {
                mma16816(acc[i][0], af[i], bf[0][0], bf[0][1]);
                mma16816(acc[i][1], af[i], bf[0][2], bf[0][3]);
                mma16816(acc[i][2], af[i], bf[1][0], bf[1][1]);
                mma16816(acc[i][3], af[i], bf[1][2], bf[1][3]);
            }
        }
    }

    #pragma unroll
    for (int i = 0; i < 4; i++)
        #pragma unroll
        for (int j = 0; j < 4; j++) {
            int r = m0 + wm + i * 16 + gid;
            int c = n0 + wn + j * 8 + tig * 2;
            if (sizeof(OutT) == 2) {
                *(__half2*)((__half*)C + (size_t)r * N + c) =
                    __floats2half2_rn(acc[i][j][0], acc[i][j][1]);
                *(__half2*)((__half*)C + (size_t)(r + 8) * N + c) =
                    __floats2half2_rn(acc[i][j][2], acc[i][j][3]);
            } else {
                float2 lo = {acc[i][j][0], acc[i][j][1]};
                float2 hi = {acc[i][j][2], acc[i][j][3]};
                *(float2*)((float*)C + (size_t)r * N + c)       = lo;
                *(float2*)((float*)C + (size_t)(r + 8) * N + c) = hi;
            }
        }
}

// ---------------------------------------------------------------------------
// Causal flash attention, fp16 tensor cores (FA2 register-resident),
// 2-stage cp.async KV pipeline, ldmatrix K fragments.
// Heavy q-tiles launched first.
// ---------------------------------------------------------------------------
#define LKV 72

__global__ __launch_bounds__(256, 2) void attn_f16_kernel(
    const __half* __restrict__ qh, const __half* __restrict__ kh,
    const __half* __restrict__ vh, __half* __restrict__ oh)
{
    __shared__ __half Ks[2][64 * LKV];
    __shared__ __half Vs[2][64 * LKV];

    int tid = threadIdx.x, wid = tid >> 5, lane = tid & 31;
    int gid = lane >> 2, tig = lane & 3;
    int q0 = (gridDim.x - 1 - blockIdx.x) * 128;
    int h  = blockIdx.y, b = blockIdx.z;
    size_t base = ((size_t)b * S_) * D_ + h * DH_;
    int wrow = wid * 16;
    int row0 = q0 + wrow + gid;

    const __half* qb = qh + base;
    const __half* kb = kh + base;
    const __half* vb = vh + base;

    int lrow = tid >> 3, loff = (tid & 7) * 8;

    // K-fragment ldmatrix base (rows = keys, col = k-offset)
    int kfoff = ((lane & 7) + ((lane >> 4) & 1) * 8) * LKV
              + ((lane >> 3) & 1) * 8;

    uint32_t qf[4][4];
    #pragma unroll
    for (int kc = 0; kc < 4; kc++) {
        const __half* p0 = &qb[(size_t)row0 * D_ + kc * 16 + tig * 2];
        const __half* p1 = &qb[(size_t)(row0 + 8) * D_ + kc * 16 + tig * 2];
        qf[kc][0] = *(const uint32_t*)(p0);
        qf[kc][1] = *(const uint32_t*)(p1);
        qf[kc][2] = *(const uint32_t*)(p0 + 8);
        qf[kc][3] = *(const uint32_t*)(p1 + 8);
    }

    float m0r = -1e30f, m1r = -1e30f, l0r = 0.0f, l1r = 0.0f;
    float oacc[8][4] = {};
    const float scale = 0.125f;

    int ntiles = (q0 >> 6) + 2;

    #pragma unroll
    for (int u = 0; u < 2; u++) {
        int row = lrow + u * 32;
        cp16(&Ks[0][row * LKV + loff], &kb[(size_t)row * D_ + loff]);
        cp16(&Vs[0][row * LKV + loff], &vb[(size_t)row * D_ + loff]);
    }
    cp_commit();

    for (int kt = 0; kt < ntiles; kt++) {
        int kv0 = kt * 64;
        int bs = kt & 1;
        if (kt + 1 < ntiles) {
            int nv0 = kv0 + 64;
            #pragma unroll
            for (int u = 0; u < 2; u++) {
                int row = lrow + u * 32;
                cp16(&Ks[bs ^ 1][row * LKV + loff],
                     &kb[(size_t)(nv0 + row) * D_ + loff]);
                cp16(&Vs[bs ^ 1][row * LKV + loff],
                     &vb[(size_t)(nv0 + row) * D_ + loff]);
            }
            cp_commit();
            asm volatile("cp.async.wait_group 1;\n");
        } else {
            asm volatile("cp.async.wait_group 0;\n");
        }
        __syncthreads();

        // S = Q K^T : ldmatrix.x4 K fragments (16 per tile)
        float sacc[8][4] = {};
        #pragma unroll
        for (int kc = 0; kc < 4; kc++) {
            #pragma unroll
            for (int j2 = 0; j2 < 4; j2++) {
                uint32_t bf[4];
                ldsm4(bf, &Ks[bs][j2 * 16 * LKV + kfoff + kc * 16]);
                mma16816(sacc[2 * j2],     qf[kc], bf[0], bf[1]);
                mma16816(sacc[2 * j2 + 1], qf[kc], bf[2], bf[3]);
            }
        }

        bool need_mask = (kv0 + 63 > q0 + wrow);
        #pragma unroll
        for (int j = 0; j < 8; j++) {
            int c0 = kv0 + j * 8 + tig * 2;
            #pragma unroll
            for (int u = 0; u < 4; u++) sacc[j][u] *= scale;
            if (need_mask) {
                if (c0     > row0)     sacc[j][0] = -1e30f;
                if (c0 + 1 > row0)     sacc[j][1] = -1e30f;
                if (c0     > row0 + 8) sacc[j][2] = -1e30f;
                if (c0 + 1 > row0 + 8) sacc[j][3] = -1e30f;
            }
        }

        float rm0 = -1e30f, rm1 = -1e30f;
        #pragma unroll
        for (int j = 0; j < 8; j++) {
            rm0 = fmaxf(rm0, fmaxf(sacc[j][0], sacc[j][1]));
            rm1 = fmaxf(rm1, fmaxf(sacc[j][2], sacc[j][3]));
        }
        rm0 = fmaxf(rm0, __shfl_xor_sync(0xffffffffu, rm0, 1));
        rm0 = fmaxf(rm0, __shfl_xor_sync(0xffffffffu, rm0, 2));
        rm1 = fmaxf(rm1, __shfl_xor_sync(0xffffffffu, rm1, 1));
        rm1 = fmaxf(rm1, __shfl_xor_sync(0xffffffffu, rm1, 2));
        float nm0 = fmaxf(m0r, rm0), nm1 = fmaxf(m1r, rm1);
        float corr0 = __expf(m0r - nm0), corr1 = __expf(m1r - nm1);
        m0r = nm0; m1r = nm1;

        float sum0 = 0.0f, sum1 = 0.0f;
        #pragma unroll
        for (int j = 0; j < 8; j++) {
            sacc[j][0] = __expf(sacc[j][0] - nm0);
            sacc[j][1] = __expf(sacc[j][1] - nm0);
            sacc[j][2] = __expf(sacc[j][2] - nm1);
            sacc[j][3] = __expf(sacc[j][3] - nm1);
            sum0 += sacc[j][0] + sacc[j][1];
            sum1 += sacc[j][2] + sacc[j][3];
        }
        sum0 += __shfl_xor_sync(0xffffffffu, sum0, 1);
        sum0 += __shfl_xor_sync(0xffffffffu, sum0, 2);
        sum1 += __shfl_xor_sync(0xffffffffu, sum1, 1);
        sum1 += __shfl_xor_sync(0xffffffffu, sum1, 2);
        l0r = l0r * corr0 + sum0;
        l1r = l1r * corr1 + sum1;

        #pragma unroll
        for (int j = 0; j < 8; j++) {
            oacc[j][0] *= corr0; oacc[j][1] *= corr0;
            oacc[j][2] *= corr1; oacc[j][3] *= corr1;
        }

        int mi = lane >> 3, rr = lane & 7;
        #pragma unroll
        for (int kc = 0; kc < 4; kc++) {
            uint32_t pf[4];
            __half2 h0 = __floats2half2_rn(sacc[2*kc][0],   sacc[2*kc][1]);
            __half2 h1 = __floats2half2_rn(sacc[2*kc][2],   sacc[2*kc][3]);
            __half2 h2 = __floats2half2_rn(sacc[2*kc+1][0], sacc[2*kc+1][1]);
            __half2 h3 = __floats2half2_rn(sacc[2*kc+1][2], sacc[2*kc+1][3]);
            pf[0] = *(uint32_t*)&h0; pf[1] = *(uint32_t*)&h1;
            pf[2] = *(uint32_t*)&h2; pf[3] = *(uint32_t*)&h3;

            #pragma unroll
            for (int jop = 0; jop < 4; jop++) {
                uint32_t r0, r1, r2, r3;
                const __half* vp = &Vs[bs][(kc * 16 + (mi & 1) * 8 + rr) * LKV
                                          + jop * 16 + (mi >> 1) * 8];
                uint32_t va = (uint32_t)__cvta_generic_to_shared(vp);
                asm volatile(
                    "ldmatrix.sync.aligned.m8n8.x4.trans.shared.b16 "
                    "{%0,%1,%2,%3}, [%4];"
                    : "=r"(r0), "=r"(r1), "=r"(r2), "=r"(r3) : "r"(va));
                mma16816(oacc[2 * jop],     pf, r0, r1);
                mma16816(oacc[2 * jop + 1], pf, r2, r3);
            }
        }
        __syncthreads();
    }

    float inv0 = 1.0f / l0r, inv1 = 1.0f / l1r;
    __half* ob = oh + base;
    #pragma unroll
    for (int j = 0; j < 8; j++) {
        int c = j * 8 + tig * 2;
        *(__half2*)&ob[(size_t)row0 * D_ + c] =
            __floats2half2_rn(oacc[j][0] * inv0, oacc[j][1] * inv0);
        *(__half2*)&ob[(size_t)(row0 + 8) * D_ + c] =
            __floats2half2_rn(oacc[j][2] * inv1, oacc[j][3] * inv1);
    }
}

// ---------------------------------------------------------------------------

extern "C" void kernel_launch(void* const* d_in, const int* in_sizes, int n_in,
                              void* d_out, int out_size)
{
    const float* x  = (const float*)d_in[0];
    const float* wq = (const float*)d_in[1];
    const float* wk = (const float*)d_in[2];
    const float* wv = (const float*)d_in[3];
    const float* wo = (const float*)d_in[4];
    float* out = (float*)d_out;

    __half *qh, *kh, *vh, *atth, *xh, *wqh, *wkh, *wvh, *woh;
    cudaGetSymbolAddress((void**)&qh,   g_qh);
    cudaGetSymbolAddress((void**)&kh,   g_kh);
    cudaGetSymbolAddress((void**)&vh,   g_vh);
    cudaGetSymbolAddress((void**)&atth, g_atth);
    cudaGetSymbolAddress((void**)&xh,   g_xh);
    cudaGetSymbolAddress((void**)&wqh,  g_wqh);
    cudaGetSymbolAddress((void**)&wkh,  g_wkh);
    cudaGetSymbolAddress((void**)&wvh,  g_wvh);
    cudaGetSymbolAddress((void**)&woh,  g_woh);

    convert_all_kernel<<<2048, 256>>>(x, wq, wk, wv, wo,
                                      xh, wqh, wkh, wvh, woh);

    cudaFuncSetAttribute(gemm_nt_f16_kernel<__half>,
                         cudaFuncAttributeMaxDynamicSharedMemorySize, GSM3);
    cudaFuncSetAttribute(gemm_nt_f16_kernel<float>,
                         cudaFuncAttributeMaxDynamicSharedMemorySize, GSM3);

    // Fused QKV projection: z selects weight/output
    dim3 gq(D_ / 128, NT_ / 128, 3);  // (8, 32, 3)
    gemm_nt_f16_kernel<__half><<<gq, 256, GSM3>>>(
        xh, wqh, wkh, wvh, qh, kh, vh, NT_, D_, D_);

    dim3 ga(S_ / 128, H_, B_);        // (16, 16, 2)
    attn_f16_kernel<<<ga, 256>>>(qh, kh, vh, atth);

    dim3 gg(D_ / 128, NT_ / 128, 1);
    gemm_nt_f16_kernel<float><<<gg, 256, GSM3>>>(
        atth, woh, woh, woh, out, out, out, NT_, D_, D_);
}

// round 14
// speedup vs baseline: 1.0832x; 1.0832x over previous
#include <cuda_runtime.h>
#include <cuda_fp16.h>
#include <stdint.h>
#include <math.h>

#define B_   2
#define S_   2048
#define D_   1024
#define H_   16
#define DH_  64
#define NT_  (B_ * S_)          // 4096 tokens
#define NQT  (S_ / 128)         // 16 q-tiles

// Scratch (allocation-free rule -> __device__ globals)
__device__ __half g_qh[NT_ * D_];
__device__ __half g_kh[NT_ * D_];
__device__ __half g_vh[NT_ * D_];
__device__ __half g_atth[NT_ * D_];
__device__ __half g_xh[NT_ * D_];
__device__ __half g_wqh[D_ * D_];
__device__ __half g_wkh[D_ * D_];
__device__ __half g_wvh[D_ * D_];
__device__ __half g_woh[D_ * D_];

__device__ __forceinline__ void mma16816(float* c, const uint32_t* a,
                                         uint32_t b0, uint32_t b1)
{
    asm volatile(
        "mma.sync.aligned.m16n8k16.row.col.f32.f16.f16.f32 "
        "{%0,%1,%2,%3}, {%4,%5,%6,%7}, {%8,%9}, {%0,%1,%2,%3};\n"
        : "+f"(c[0]), "+f"(c[1]), "+f"(c[2]), "+f"(c[3])
        : "r"(a[0]), "r"(a[1]), "r"(a[2]), "r"(a[3]), "r"(b0), "r"(b1));
}

__device__ __forceinline__ void ldsm4(uint32_t* r, const void* p)
{
    uint32_t a = (uint32_t)__cvta_generic_to_shared(p);
    asm volatile("ldmatrix.sync.aligned.m8n8.x4.shared.b16 {%0,%1,%2,%3}, [%4];"
                 : "=r"(r[0]), "=r"(r[1]), "=r"(r[2]), "=r"(r[3]) : "r"(a));
}

__device__ __forceinline__ void cp16(void* smem, const void* gmem)
{
    uint32_t sa = (uint32_t)__cvta_generic_to_shared(smem);
    asm volatile("cp.async.cg.shared.global [%0], [%1], 16;\n"
                 :: "r"(sa), "l"(gmem));
}
__device__ __forceinline__ void cp_commit()
{
    asm volatile("cp.async.commit_group;\n");
}

// ---------------------------------------------------------------------------
// Fused fp32 -> fp16 convert for x + 4 weights (8M elements total).
// ---------------------------------------------------------------------------
__global__ __launch_bounds__(256) void convert_all_kernel(
    const float* __restrict__ x,  const float* __restrict__ wq,
    const float* __restrict__ wk, const float* __restrict__ wv,
    const float* __restrict__ wo,
    __half* __restrict__ xh, __half* __restrict__ wqh,
    __half* __restrict__ wkh, __half* __restrict__ wvh,
    __half* __restrict__ woh)
{
    size_t gi = ((size_t)blockIdx.x * 256 + threadIdx.x) * 16;
    int seg = (int)(gi >> 20);
    const float* in; __half* out; size_t off;
    if (seg < 4)      { in = x;  out = xh;  off = gi; }
    else if (seg == 4){ in = wq; out = wqh; off = gi - (4u << 20); }
    else if (seg == 5){ in = wk; out = wkh; off = gi - (5u << 20); }
    else if (seg == 6){ in = wv; out = wvh; off = gi - (6u << 20); }
    else              { in = wo; out = woh; off = gi - (7u << 20); }

    float4 v0 = *(const float4*)&in[off];
    float4 v1 = *(const float4*)&in[off + 4];
    float4 v2 = *(const float4*)&in[off + 8];
    float4 v3 = *(const float4*)&in[off + 12];
    __half2 h[8];
    h[0] = __floats2half2_rn(v0.x, v0.y); h[1] = __floats2half2_rn(v0.z, v0.w);
    h[2] = __floats2half2_rn(v1.x, v1.y); h[3] = __floats2half2_rn(v1.z, v1.w);
    h[4] = __floats2half2_rn(v2.x, v2.y); h[5] = __floats2half2_rn(v2.z, v2.w);
    h[6] = __floats2half2_rn(v3.x, v3.y); h[7] = __floats2half2_rn(v3.z, v3.w);
    *(int4*)&out[off]     = *(int4*)&h[0];
    *(int4*)&out[off + 8] = *(int4*)&h[4];
}

// ---------------------------------------------------------------------------
// C[M,N] = A[M,K] @ W[N,K]^T  fp16 mma, f32 accum, OutT epilogue.
// Block 128x128, BK=64, 8 warps (2x4), warp tile 64x32 (4x4 mma grid).
// 3-stage cp.async ring, ONE syncthreads per slab, ldmatrix fragments.
// blockIdx.z picks W/C pair (QKV fuse).  (mma.sync ceiling reached; frozen.)
// ---------------------------------------------------------------------------
#define LDG3 72                      // pitch in halves (144 B)
#define GT3  (128 * LDG3)            // halves per operand tile
#define GSM3 (3 * 2 * GT3 * 2)       // bytes: 3 stages x (A+B) x 2B = 110592

template <typename OutT>
__global__ __launch_bounds__(256, 2) void gemm_nt_f16_kernel(
    const __half* __restrict__ A,
    const __half* __restrict__ W0, const __half* __restrict__ W1,
    const __half* __restrict__ W2,
    OutT* __restrict__ C0, OutT* __restrict__ C1, OutT* __restrict__ C2,
    int M, int N, int K)
{
    extern __shared__ __half smem[];
    const __half* W = (blockIdx.z == 0) ? W0 : (blockIdx.z == 1) ? W1 : W2;
    OutT*         C = (blockIdx.z == 0) ? C0 : (blockIdx.z == 1) ? C1 : C2;

    int tid  = threadIdx.x;
    int wid  = tid >> 5, lane = tid & 31;
    int gid  = lane >> 2, tig = lane & 3;
    int wm   = (wid & 1) * 64;
    int wn   = (wid >> 1) * 32;
    int m0   = blockIdx.y * 128;
    int n0   = blockIdx.x * 128;

    int aoff = (wm + (lane & 15)) * LDG3 + (lane >> 4) * 8;
    int boff = (wn + (lane & 7) + ((lane >> 4) & 1) * 8) * LDG3
             + ((lane >> 3) & 1) * 8;

    float acc[4][4][4] = {};

    const int NIT = K / 64;          // 16

    auto load_stage = [&](int slot, int k0) {
        __half* as = smem + slot * 2 * GT3;
        __half* bs = as + GT3;
        #pragma unroll
        for (int u = 0; u < 4; u++) {
            int c = tid + u * 256;              // 0..1023
            int row = c >> 3, col = (c & 7) * 8;
            cp16(&as[row * LDG3 + col], &A[(size_t)(m0 + row) * K + k0 + col]);
            cp16(&bs[row * LDG3 + col], &W[(size_t)(n0 + row) * K + k0 + col]);
        }
        cp_commit();
    };

    load_stage(0, 0);
    load_stage(1, 64);

    for (int t = 0; t < NIT; t++) {
        if (t + 1 < NIT) asm volatile("cp.async.wait_group 1;\n");
        else             asm volatile("cp.async.wait_group 0;\n");
        __syncthreads();

        if (t + 2 < NIT) load_stage((t + 2) % 3, (t + 2) * 64);

        const __half* as = smem + (t % 3) * 2 * GT3;
        const __half* bs = as + GT3;

        #pragma unroll
        for (int ks = 0; ks < 4; ks++) {
            int kb = ks * 16;
            uint32_t af[4][4], bf[2][4];
            #pragma unroll
            for (int i = 0; i < 4; i++)
                ldsm4(af[i], as + aoff + i * 16 * LDG3 + kb);
            #pragma unroll
            for (int jp = 0; jp < 2; jp++)
                ldsm4(bf[jp], bs + boff + jp * 16 * LDG3 + kb);
            #pragma unroll
            for (int i = 0; i < 4; i++) {
                mma16816(acc[i][0], af[i], bf[0][0], bf[0][1]);
                mma16816(acc[i][1], af[i], bf[0][2], bf[0][3]);
                mma16816(acc[i][2], af[i], bf[1][0], bf[1][1]);
                mma16816(acc[i][3], af[i], bf[1][2], bf[1][3]);
            }
        }
    }

    #pragma unroll
    for (int i = 0; i < 4; i++)
        #pragma unroll
        for (int j = 0; j < 4; j++) {
            int r = m0 + wm + i * 16 + gid;
            int c = n0 + wn + j * 8 + tig * 2;
            if (sizeof(OutT) == 2) {
                *(__half2*)((__half*)C + (size_t)r * N + c) =
                    __floats2half2_rn(acc[i][j][0], acc[i][j][1]);
                *(__half2*)((__half*)C + (size_t)(r + 8) * N + c) =
                    __floats2half2_rn(acc[i][j][2], acc[i][j][3]);
            } else {
                float2 lo = {acc[i][j][0], acc[i][j][1]};
                float2 hi = {acc[i][j][2], acc[i][j][3]};
                *(float2*)((float*)C + (size_t)r * N + c)       = lo;
                *(float2*)((float*)C + (size_t)(r + 8) * N + c) = hi;
            }
        }
}

// ---------------------------------------------------------------------------
// Causal flash attention, fp16 tensor cores (FA2 register-resident),
// 2-stage cp.async KV pipeline, ldmatrix K fragments.
// PAIRED SCHEDULE: block p handles q-tiles p and NQT-1-p sequentially ->
// every block does exactly 34 KV tiles; grid 8x16x2 = 256 blocks = 1 wave.
// ---------------------------------------------------------------------------
#define LKV 72

__global__ __launch_bounds__(256, 2) void attn_f16_kernel(
    const __half* __restrict__ qh, const __half* __restrict__ kh,
    const __half* __restrict__ vh, __half* __restrict__ oh)
{
    __shared__ __half Ks[2][64 * LKV];
    __shared__ __half Vs[2][64 * LKV];

    int tid = threadIdx.x, wid = tid >> 5, lane = tid & 31;
    int gid = lane >> 2, tig = lane & 3;
    int h  = blockIdx.y, b = blockIdx.z;
    size_t base = ((size_t)b * S_) * D_ + h * DH_;
    int wrow = wid * 16;

    const __half* qb = qh + base;
    const __half* kb = kh + base;
    const __half* vb = vh + base;
    __half* ob = oh + base;

    int lrow = tid >> 3, loff = (tid & 7) * 8;
    int kfoff = ((lane & 7) + ((lane >> 4) & 1) * 8) * LKV
              + ((lane >> 3) & 1) * 8;
    const float scale = 0.125f;

    #pragma unroll 1
    for (int sub = 0; sub < 2; sub++) {
        int qt = (sub == 0) ? (int)blockIdx.x : (NQT - 1 - (int)blockIdx.x);
        int q0 = qt * 128;
        int row0 = q0 + wrow + gid;

        // Q fragments (per sub-tile)
        uint32_t qf[4][4];
        #pragma unroll
        for (int kc = 0; kc < 4; kc++) {
            const __half* p0 = &qb[(size_t)row0 * D_ + kc * 16 + tig * 2];
            const __half* p1 = &qb[(size_t)(row0 + 8) * D_ + kc * 16 + tig * 2];
            qf[kc][0] = *(const uint32_t*)(p0);
            qf[kc][1] = *(const uint32_t*)(p1);
            qf[kc][2] = *(const uint32_t*)(p0 + 8);
            qf[kc][3] = *(const uint32_t*)(p1 + 8);
        }

        float m0r = -1e30f, m1r = -1e30f, l0r = 0.0f, l1r = 0.0f;
        float oacc[8][4] = {};

        int ntiles = (q0 >> 6) + 2;

        #pragma unroll
        for (int u = 0; u < 2; u++) {
            int row = lrow + u * 32;
            cp16(&Ks[0][row * LKV + loff], &kb[(size_t)row * D_ + loff]);
            cp16(&Vs[0][row * LKV + loff], &vb[(size_t)row * D_ + loff]);
        }
        cp_commit();

        for (int kt = 0; kt < ntiles; kt++) {
            int kv0 = kt * 64;
            int bs = kt & 1;
            if (kt + 1 < ntiles) {
                int nv0 = kv0 + 64;
                #pragma unroll
                for (int u = 0; u < 2; u++) {
                    int row = lrow + u * 32;
                    cp16(&Ks[bs ^ 1][row * LKV + loff],
                         &kb[(size_t)(nv0 + row) * D_ + loff]);
                    cp16(&Vs[bs ^ 1][row * LKV + loff],
                         &vb[(size_t)(nv0 + row) * D_ + loff]);
                }
                cp_commit();
                asm volatile("cp.async.wait_group 1;\n");
            } else {
                asm volatile("cp.async.wait_group 0;\n");
            }
            __syncthreads();

            // S = Q K^T : ldmatrix.x4 K fragments
            float sacc[8][4] = {};
            #pragma unroll
            for (int kc = 0; kc < 4; kc++) {
                #pragma unroll
                for (int j2 = 0; j2 < 4; j2++) {
                    uint32_t bf[4];
                    ldsm4(bf, &Ks[bs][j2 * 16 * LKV + kfoff + kc * 16]);
                    mma16816(sacc[2 * j2],     qf[kc], bf[0], bf[1]);
                    mma16816(sacc[2 * j2 + 1], qf[kc], bf[2], bf[3]);
                }
            }

            bool need_mask = (kv0 + 63 > q0 + wrow);
            #pragma unroll
            for (int j = 0; j < 8; j++) {
                int c0 = kv0 + j * 8 + tig * 2;
                #pragma unroll
                for (int u = 0; u < 4; u++) sacc[j][u] *= scale;
                if (need_mask) {
                    if (c0     > row0)     sacc[j][0] = -1e30f;
                    if (c0 + 1 > row0)     sacc[j][1] = -1e30f;
                    if (c0     > row0 + 8) sacc[j][2] = -1e30f;
                    if (c0 + 1 > row0 + 8) sacc[j][3] = -1e30f;
                }
            }

            float rm0 = -1e30f, rm1 = -1e30f;
            #pragma unroll
            for (int j = 0; j < 8; j++) {
                rm0 = fmaxf(rm0, fmaxf(sacc[j][0], sacc[j][1]));
                rm1 = fmaxf(rm1, fmaxf(sacc[j][2], sacc[j][3]));
            }
            rm0 = fmaxf(rm0, __shfl_xor_sync(0xffffffffu, rm0, 1));
            rm0 = fmaxf(rm0, __shfl_xor_sync(0xffffffffu, rm0, 2));
            rm1 = fmaxf(rm1, __shfl_xor_sync(0xffffffffu, rm1, 1));
            rm1 = fmaxf(rm1, __shfl_xor_sync(0xffffffffu, rm1, 2));
            float nm0 = fmaxf(m0r, rm0), nm1 = fmaxf(m1r, rm1);
            float corr0 = __expf(m0r - nm0), corr1 = __expf(m1r - nm1);
            m0r = nm0; m1r = nm1;

            float sum0 = 0.0f, sum1 = 0.0f;
            #pragma unroll
            for (int j = 0; j < 8; j++) {
                sacc[j][0] = __expf(sacc[j][0] - nm0);
                sacc[j][1] = __expf(sacc[j][1] - nm0);
                sacc[j][2] = __expf(sacc[j][2] - nm1);
                sacc[j][3] = __expf(sacc[j][3] - nm1);
                sum0 += sacc[j][0] + sacc[j][1];
                sum1 += sacc[j][2] + sacc[j][3];
            }
            sum0 += __shfl_xor_sync(0xffffffffu, sum0, 1);
            sum0 += __shfl_xor_sync(0xffffffffu, sum0, 2);
            sum1 += __shfl_xor_sync(0xffffffffu, sum1, 1);
            sum1 += __shfl_xor_sync(0xffffffffu, sum1, 2);
            l0r = l0r * corr0 + sum0;
            l1r = l1r * corr1 + sum1;

            #pragma unroll
            for (int j = 0; j < 8; j++) {
                oacc[j][0] *= corr0; oacc[j][1] *= corr0;
                oacc[j][2] *= corr1; oacc[j][3] *= corr1;
            }

            int mi = lane >> 3, rr = lane & 7;
            #pragma unroll
            for (int kc = 0; kc < 4; kc++) {
                uint32_t pf[4];
                __half2 h0 = __floats2half2_rn(sacc[2*kc][0],   sacc[2*kc][1]);
                __half2 h1 = __floats2half2_rn(sacc[2*kc][2],   sacc[2*kc][3]);
                __half2 h2 = __floats2half2_rn(sacc[2*kc+1][0], sacc[2*kc+1][1]);
                __half2 h3 = __floats2half2_rn(sacc[2*kc+1][2], sacc[2*kc+1][3]);
                pf[0] = *(uint32_t*)&h0; pf[1] = *(uint32_t*)&h1;
                pf[2] = *(uint32_t*)&h2; pf[3] = *(uint32_t*)&h3;

                #pragma unroll
                for (int jop = 0; jop < 4; jop++) {
                    uint32_t r0, r1, r2, r3;
                    const __half* vp = &Vs[bs][(kc * 16 + (mi & 1) * 8 + rr) * LKV
                                              + jop * 16 + (mi >> 1) * 8];
                    uint32_t va = (uint32_t)__cvta_generic_to_shared(vp);
                    asm volatile(
                        "ldmatrix.sync.aligned.m8n8.x4.trans.shared.b16 "
                        "{%0,%1,%2,%3}, [%4];"
                        : "=r"(r0), "=r"(r1), "=r"(r2), "=r"(r3) : "r"(va));
                    mma16816(oacc[2 * jop],     pf, r0, r1);
                    mma16816(oacc[2 * jop + 1], pf, r2, r3);
                }
            }
            __syncthreads();
        }

        // normalize + store fp16
        float inv0 = 1.0f / l0r, inv1 = 1.0f / l1r;
        #pragma unroll
        for (int j = 0; j < 8; j++) {
            int c = j * 8 + tig * 2;
            *(__half2*)&ob[(size_t)row0 * D_ + c] =
                __floats2half2_rn(oacc[j][0] * inv0, oacc[j][1] * inv0);
            *(__half2*)&ob[(size_t)(row0 + 8) * D_ + c] =
                __floats2half2_rn(oacc[j][2] * inv1, oacc[j][3] * inv1);
        }
    }
}

// ---------------------------------------------------------------------------

extern "C" void kernel_launch(void* const* d_in, const int* in_sizes, int n_in,
                              void* d_out, int out_size)
{
    const float* x  = (const float*)d_in[0];
    const float* wq = (const float*)d_in[1];
    const float* wk = (const float*)d_in[2];
    const float* wv = (const float*)d_in[3];
    const float* wo = (const float*)d_in[4];
    float* out = (float*)d_out;

    __half *qh, *kh, *vh, *atth, *xh, *wqh, *wkh, *wvh, *woh;
    cudaGetSymbolAddress((void**)&qh,   g_qh);
    cudaGetSymbolAddress((void**)&kh,   g_kh);
    cudaGetSymbolAddress((void**)&vh,   g_vh);
    cudaGetSymbolAddress((void**)&atth, g_atth);
    cudaGetSymbolAddress((void**)&xh,   g_xh);
    cudaGetSymbolAddress((void**)&wqh,  g_wqh);
    cudaGetSymbolAddress((void**)&wkh,  g_wkh);
    cudaGetSymbolAddress((void**)&wvh,  g_wvh);
    cudaGetSymbolAddress((void**)&woh,  g_woh);

    convert_all_kernel<<<2048, 256>>>(x, wq, wk, wv, wo,
                                      xh, wqh, wkh, wvh, woh);

    cudaFuncSetAttribute(gemm_nt_f16_kernel<__half>,
                         cudaFuncAttributeMaxDynamicSharedMemorySize, GSM3);
    cudaFuncSetAttribute(gemm_nt_f16_kernel<float>,
                         cudaFuncAttributeMaxDynamicSharedMemorySize, GSM3);

    // Fused QKV projection: z selects weight/output
    dim3 gq(D_ / 128, NT_ / 128, 3);  // (8, 32, 3)
    gemm_nt_f16_kernel<__half><<<gq, 256, GSM3>>>(
        xh, wqh, wkh, wvh, qh, kh, vh, NT_, D_, D_);

    // Paired attention: 8x16x2 = 256 blocks, uniform 34 KV tiles each
    dim3 ga(NQT / 2, H_, B_);         // (8, 16, 2)
    attn_f16_kernel<<<ga, 256>>>(qh, kh, vh, atth);

    dim3 gg(D_ / 128, NT_ / 128, 1);
    gemm_nt_f16_kernel<float><<<gg, 256, GSM3>>>(
        atth, woh, woh, woh, out, out, out, NT_, D_, D_);
}

// round 15
// speedup vs baseline: 1.1380x; 1.0506x over previous
#include <cuda_runtime.h>
#include <cuda_fp16.h>
#include <stdint.h>
#include <math.h>

#define B_   2
#define S_   2048
#define D_   1024
#define H_   16
#define DH_  64
#define NT_  (B_ * S_)          // 4096 tokens
#define NQT  (S_ / 128)         // 16 q-tiles

// Scratch (allocation-free rule -> __device__ globals)
__device__ __half g_qh[NT_ * D_];
__device__ __half g_kh[NT_ * D_];
__device__ __half g_vh[NT_ * D_];
__device__ __half g_atth[NT_ * D_];
__device__ __half g_xh[NT_ * D_];
__device__ __half g_wqh[D_ * D_];
__device__ __half g_wkh[D_ * D_];
__device__ __half g_wvh[D_ * D_];
__device__ __half g_woh[D_ * D_];

__device__ __forceinline__ void mma16816(float* c, const uint32_t* a,
                                         uint32_t b0, uint32_t b1)
{
    asm volatile(
        "mma.sync.aligned.m16n8k16.row.col.f32.f16.f16.f32 "
        "{%0,%1,%2,%3}, {%4,%5,%6,%7}, {%8,%9}, {%0,%1,%2,%3};\n"
        : "+f"(c[0]), "+f"(c[1]), "+f"(c[2]), "+f"(c[3])
        : "r"(a[0]), "r"(a[1]), "r"(a[2]), "r"(a[3]), "r"(b0), "r"(b1));
}

__device__ __forceinline__ void ldsm4(uint32_t* r, const void* p)
{
    uint32_t a = (uint32_t)__cvta_generic_to_shared(p);
    asm volatile("ldmatrix.sync.aligned.m8n8.x4.shared.b16 {%0,%1,%2,%3}, [%4];"
                 : "=r"(r[0]), "=r"(r[1]), "=r"(r[2]), "=r"(r[3]) : "r"(a));
}

__device__ __forceinline__ void cp16(void* smem, const void* gmem)
{
    uint32_t sa = (uint32_t)__cvta_generic_to_shared(smem);
    asm volatile("cp.async.cg.shared.global [%0], [%1], 16;\n"
                 :: "r"(sa), "l"(gmem));
}
__device__ __forceinline__ void cp_commit()
{
    asm volatile("cp.async.commit_group;\n");
}

__device__ __forceinline__ uint32_t ex2_f16x2(float d0, float d1)
{
    __half2 h = __floats2half2_rn(d0, d1);
    uint32_t hp = *(uint32_t*)&h, p;
    asm("ex2.approx.f16x2 %0, %1;" : "=r"(p) : "r"(hp));
    return p;
}

// ---------------------------------------------------------------------------
// Fused fp32 -> fp16 convert for x + 4 weights (8M elements total).
// ---------------------------------------------------------------------------
__global__ __launch_bounds__(256) void convert_all_kernel(
    const float* __restrict__ x,  const float* __restrict__ wq,
    const float* __restrict__ wk, const float* __restrict__ wv,
    const float* __restrict__ wo,
    __half* __restrict__ xh, __half* __restrict__ wqh,
    __half* __restrict__ wkh, __half* __restrict__ wvh,
    __half* __restrict__ woh)
{
    size_t gi = ((size_t)blockIdx.x * 256 + threadIdx.x) * 16;
    int seg = (int)(gi >> 20);
    const float* in; __half* out; size_t off;
    if (seg < 4)      { in = x;  out = xh;  off = gi; }
    else if (seg == 4){ in = wq; out = wqh; off = gi - (4u << 20); }
    else if (seg == 5){ in = wk; out = wkh; off = gi - (5u << 20); }
    else if (seg == 6){ in = wv; out = wvh; off = gi - (6u << 20); }
    else              { in = wo; out = woh; off = gi - (7u << 20); }

    float4 v0 = *(const float4*)&in[off];
    float4 v1 = *(const float4*)&in[off + 4];
    float4 v2 = *(const float4*)&in[off + 8];
    float4 v3 = *(const float4*)&in[off + 12];
    __half2 h[8];
    h[0] = __floats2half2_rn(v0.x, v0.y); h[1] = __floats2half2_rn(v0.z, v0.w);
    h[2] = __floats2half2_rn(v1.x, v1.y); h[3] = __floats2half2_rn(v1.z, v1.w);
    h[4] = __floats2half2_rn(v2.x, v2.y); h[5] = __floats2half2_rn(v2.z, v2.w);
    h[6] = __floats2half2_rn(v3.x, v3.y); h[7] = __floats2half2_rn(v3.z, v3.w);
    *(int4*)&out[off]     = *(int4*)&h[0];
    *(int4*)&out[off + 8] = *(int4*)&h[4];
}

// ---------------------------------------------------------------------------
// C[M,N] = A[M,K] @ W[N,K]^T  fp16 mma, f32 accum, OutT epilogue.
// Block 128x128, BK=64, 8 warps (2x4), warp tile 64x32 (4x4 mma grid).
// 3-stage cp.async ring, ONE syncthreads per slab, ldmatrix fragments.
// blockIdx.z picks W/C pair (QKV fuse).  (mma.sync ceiling reached; frozen.)
// ---------------------------------------------------------------------------
#define LDG3 72                      // pitch in halves (144 B)
#define GT3  (128 * LDG3)            // halves per operand tile
#define GSM3 (3 * 2 * GT3 * 2)       // bytes: 3 stages x (A+B) x 2B = 110592

template <typename OutT>
__global__ __launch_bounds__(256, 2) void gemm_nt_f16_kernel(
    const __half* __restrict__ A,
    const __half* __restrict__ W0, const __half* __restrict__ W1,
    const __half* __restrict__ W2,
    OutT* __restrict__ C0, OutT* __restrict__ C1, OutT* __restrict__ C2,
    int M, int N, int K)
{
    extern __shared__ __half smem[];
    const __half* W = (blockIdx.z == 0) ? W0 : (blockIdx.z == 1) ? W1 : W2;
    OutT*         C = (blockIdx.z == 0) ? C0 : (blockIdx.z == 1) ? C1 : C2;

    int tid  = threadIdx.x;
    int wid  = tid >> 5, lane = tid & 31;
    int gid  = lane >> 2, tig = lane & 3;
    int wm   = (wid & 1) * 64;
    int wn   = (wid >> 1) * 32;
    int m0   = blockIdx.y * 128;
    int n0   = blockIdx.x * 128;

    int aoff = (wm + (lane & 15)) * LDG3 + (lane >> 4) * 8;
    int boff = (wn + (lane & 7) + ((lane >> 4) & 1) * 8) * LDG3
             + ((lane >> 3) & 1) * 8;

    float acc[4][4][4] = {};

    const int NIT = K / 64;          // 16

    auto load_stage = [&](int slot, int k0) {
        __half* as = smem + slot * 2 * GT3;
        __half* bs = as + GT3;
        #pragma unroll
        for (int u = 0; u < 4; u++) {
            int c = tid + u * 256;              // 0..1023
            int row = c >> 3, col = (c & 7) * 8;
            cp16(&as[row * LDG3 + col], &A[(size_t)(m0 + row) * K + k0 + col]);
            cp16(&bs[row * LDG3 + col], &W[(size_t)(n0 + row) * K + k0 + col]);
        }
        cp_commit();
    };

    load_stage(0, 0);
    load_stage(1, 64);

    for (int t = 0; t < NIT; t++) {
        if (t + 1 < NIT) asm volatile("cp.async.wait_group 1;\n");
        else             asm volatile("cp.async.wait_group 0;\n");
        __syncthreads();

        if (t + 2 < NIT) load_stage((t + 2) % 3, (t + 2) * 64);

        const __half* as = smem + (t % 3) * 2 * GT3;
        const __half* bs = as + GT3;

        #pragma unroll
        for (int ks = 0; ks < 4; ks++) {
            int kb = ks * 16;
            uint32_t af[4][4], bf[2][4];
            #pragma unroll
            for (int i = 0; i < 4; i++)
                ldsm4(af[i], as + aoff + i * 16 * LDG3 + kb);
            #pragma unroll
            for (int jp = 0; jp < 2; jp++)
                ldsm4(bf[jp], bs + boff + jp * 16 * LDG3 + kb);
            #pragma unroll
            for (int i = 0; i < 4; i++) {
                mma16816(acc[i][0], af[i], bf[0][0], bf[0][1]);
                mma16816(acc[i][1], af[i], bf[0][2], bf[0][3]);
                mma16816(acc[i][2], af[i], bf[1][0], bf[1][1]);
                mma16816(acc[i][3], af[i], bf[1][2], bf[1][3]);
            }
        }
    }

    #pragma unroll
    for (int i = 0; i < 4; i++)
        #pragma unroll
        for (int j = 0; j < 4; j++) {
            int r = m0 + wm + i * 16 + gid;
            int c = n0 + wn + j * 8 + tig * 2;
            if (sizeof(OutT) == 2) {
                *(__half2*)((__half*)C + (size_t)r * N + c) =
                    __floats2half2_rn(acc[i][j][0], acc[i][j][1]);
                *(__half2*)((__half*)C + (size_t)(r + 8) * N + c) =
                    __floats2half2_rn(acc[i][j][2], acc[i][j][3]);
            } else {
                float2 lo = {acc[i][j][0], acc[i][j][1]};
                float2 hi = {acc[i][j][2], acc[i][j][3]};
                *(float2*)((float*)C + (size_t)r * N + c)       = lo;
                *(float2*)((float*)C + (size_t)(r + 8) * N + c) = hi;
            }
        }
}

// ---------------------------------------------------------------------------
// Causal flash attention, fp16 tensor cores (FA2 register-resident),
// 2-stage cp.async KV pipeline, ldmatrix K fragments,
// f16x2 softmax exp (ex2.approx.f16x2) feeding PV fragments directly.
// PAIRED SCHEDULE: block p handles q-tiles p and NQT-1-p (34 KV tiles each).
// ---------------------------------------------------------------------------
#define LKV 72

__global__ __launch_bounds__(256, 2) void attn_f16_kernel(
    const __half* __restrict__ qh, const __half* __restrict__ kh,
    const __half* __restrict__ vh, __half* __restrict__ oh)
{
    __shared__ __half Ks[2][64 * LKV];
    __shared__ __half Vs[2][64 * LKV];

    int tid = threadIdx.x, wid = tid >> 5, lane = tid & 31;
    int gid = lane >> 2, tig = lane & 3;
    int h  = blockIdx.y, b = blockIdx.z;
    size_t base = ((size_t)b * S_) * D_ + h * DH_;
    int wrow = wid * 16;

    const __half* qb = qh + base;
    const __half* kb = kh + base;
    const __half* vb = vh + base;
    __half* ob = oh + base;

    int lrow = tid >> 3, loff = (tid & 7) * 8;
    int kfoff = ((lane & 7) + ((lane >> 4) & 1) * 8) * LKV
              + ((lane >> 3) & 1) * 8;
    const float c2 = 0.125f * 1.44269504f;   // scale * log2(e)

    #pragma unroll 1
    for (int sub = 0; sub < 2; sub++) {
        int qt = (sub == 0) ? (int)blockIdx.x : (NQT - 1 - (int)blockIdx.x);
        int q0 = qt * 128;
        int row0 = q0 + wrow + gid;

        uint32_t qf[4][4];
        #pragma unroll
        for (int kc = 0; kc < 4; kc++) {
            const __half* p0 = &qb[(size_t)row0 * D_ + kc * 16 + tig * 2];
            const __half* p1 = &qb[(size_t)(row0 + 8) * D_ + kc * 16 + tig * 2];
            qf[kc][0] = *(const uint32_t*)(p0);
            qf[kc][1] = *(const uint32_t*)(p1);
            qf[kc][2] = *(const uint32_t*)(p0 + 8);
            qf[kc][3] = *(const uint32_t*)(p1 + 8);
        }

        // m in RAW score domain (unscaled); exp domain handled via c2
        float m0r = -1e30f, m1r = -1e30f, l0r = 0.0f, l1r = 0.0f;
        float oacc[8][4] = {};

        int ntiles = (q0 >> 6) + 2;

        #pragma unroll
        for (int u = 0; u < 2; u++) {
            int row = lrow + u * 32;
            cp16(&Ks[0][row * LKV + loff], &kb[(size_t)row * D_ + loff]);
            cp16(&Vs[0][row * LKV + loff], &vb[(size_t)row * D_ + loff]);
        }
        cp_commit();

        for (int kt = 0; kt < ntiles; kt++) {
            int kv0 = kt * 64;
            int bs = kt & 1;
            if (kt + 1 < ntiles) {
                int nv0 = kv0 + 64;
                #pragma unroll
                for (int u = 0; u < 2; u++) {
                    int row = lrow + u * 32;
                    cp16(&Ks[bs ^ 1][row * LKV + loff],
                         &kb[(size_t)(nv0 + row) * D_ + loff]);
                    cp16(&Vs[bs ^ 1][row * LKV + loff],
                         &vb[(size_t)(nv0 + row) * D_ + loff]);
                }
                cp_commit();
                asm volatile("cp.async.wait_group 1;\n");
            } else {
                asm volatile("cp.async.wait_group 0;\n");
            }
            __syncthreads();

            // S = Q K^T (raw scores)
            float sacc[8][4] = {};
            #pragma unroll
            for (int kc = 0; kc < 4; kc++) {
                #pragma unroll
                for (int j2 = 0; j2 < 4; j2++) {
                    uint32_t bf[4];
                    ldsm4(bf, &Ks[bs][j2 * 16 * LKV + kfoff + kc * 16]);
                    mma16816(sacc[2 * j2],     qf[kc], bf[0], bf[1]);
                    mma16816(sacc[2 * j2 + 1], qf[kc], bf[2], bf[3]);
                }
            }

            // causal mask (raw domain)
            bool need_mask = (kv0 + 63 > q0 + wrow);
            if (need_mask) {
                #pragma unroll
                for (int j = 0; j < 8; j++) {
                    int c0 = kv0 + j * 8 + tig * 2;
                    if (c0     > row0)     sacc[j][0] = -1e30f;
                    if (c0 + 1 > row0)     sacc[j][1] = -1e30f;
                    if (c0     > row0 + 8) sacc[j][2] = -1e30f;
                    if (c0 + 1 > row0 + 8) sacc[j][3] = -1e30f;
                }
            }

            // row max (raw domain)
            float rm0 = -1e30f, rm1 = -1e30f;
            #pragma unroll
            for (int j = 0; j < 8; j++) {
                rm0 = fmaxf(rm0, fmaxf(sacc[j][0], sacc[j][1]));
                rm1 = fmaxf(rm1, fmaxf(sacc[j][2], sacc[j][3]));
            }
            rm0 = fmaxf(rm0, __shfl_xor_sync(0xffffffffu, rm0, 1));
            rm0 = fmaxf(rm0, __shfl_xor_sync(0xffffffffu, rm0, 2));
            rm1 = fmaxf(rm1, __shfl_xor_sync(0xffffffffu, rm1, 1));
            rm1 = fmaxf(rm1, __shfl_xor_sync(0xffffffffu, rm1, 2));
            float nm0 = fmaxf(m0r, rm0), nm1 = fmaxf(m1r, rm1);
            float corr0 = exp2f((m0r - nm0) * c2);
            float corr1 = exp2f((m1r - nm1) * c2);
            m0r = nm0; m1r = nm1;
            float nc0 = nm0 * c2, nc1 = nm1 * c2;

            // p = 2^(s*c2 - nm*c2) in f16x2 — IS the PV fragment
            uint32_t ph[8][2];
            float sum0 = 0.0f, sum1 = 0.0f;
            #pragma unroll
            for (int j = 0; j < 8; j++) {
                float d0 = fmaf(sacc[j][0], c2, -nc0);
                float d1 = fmaf(sacc[j][1], c2, -nc0);
                float d2 = fmaf(sacc[j][2], c2, -nc1);
                float d3 = fmaf(sacc[j][3], c2, -nc1);
                ph[j][0] = ex2_f16x2(d0, d1);
                ph[j][1] = ex2_f16x2(d2, d3);
                float2 f01 = __half22float2(*(__half2*)&ph[j][0]);
                float2 f23 = __half22float2(*(__half2*)&ph[j][1]);
                sum0 += f01.x + f01.y;
                sum1 += f23.x + f23.y;
            }
            sum0 += __shfl_xor_sync(0xffffffffu, sum0, 1);
            sum0 += __shfl_xor_sync(0xffffffffu, sum0, 2);
            sum1 += __shfl_xor_sync(0xffffffffu, sum1, 1);
            sum1 += __shfl_xor_sync(0xffffffffu, sum1, 2);
            l0r = l0r * corr0 + sum0;
            l1r = l1r * corr1 + sum1;

            #pragma unroll
            for (int j = 0; j < 8; j++) {
                oacc[j][0] *= corr0; oacc[j][1] *= corr0;
                oacc[j][2] *= corr1; oacc[j][3] *= corr1;
            }

            // O += P @ V
            int mi = lane >> 3, rr = lane & 7;
            #pragma unroll
            for (int kc = 0; kc < 4; kc++) {
                uint32_t pf[4];
                pf[0] = ph[2 * kc][0];
                pf[1] = ph[2 * kc][1];
                pf[2] = ph[2 * kc + 1][0];
                pf[3] = ph[2 * kc + 1][1];

                #pragma unroll
                for (int jop = 0; jop < 4; jop++) {
                    uint32_t r0, r1, r2, r3;
                    const __half* vp = &Vs[bs][(kc * 16 + (mi & 1) * 8 + rr) * LKV
                                              + jop * 16 + (mi >> 1) * 8];
                    uint32_t va = (uint32_t)__cvta_generic_to_shared(vp);
                    asm volatile(
                        "ldmatrix.sync.aligned.m8n8.x4.trans.shared.b16 "
                        "{%0,%1,%2,%3}, [%4];"
                        : "=r"(r0), "=r"(r1), "=r"(r2), "=r"(r3) : "r"(va));
                    mma16816(oacc[2 * jop],     pf, r0, r1);
                    mma16816(oacc[2 * jop + 1], pf, r2, r3);
                }
            }
            __syncthreads();
        }

        // normalize + store fp16
        float inv0 = 1.0f / l0r, inv1 = 1.0f / l1r;
        #pragma unroll
        for (int j = 0; j < 8; j++) {
            int c = j * 8 + tig * 2;
            *(__half2*)&ob[(size_t)row0 * D_ + c] =
                __floats2half2_rn(oacc[j][0] * inv0, oacc[j][1] * inv0);
            *(__half2*)&ob[(size_t)(row0 + 8) * D_ + c] =
                __floats2half2_rn(oacc[j][2] * inv1, oacc[j][3] * inv1);
        }
    }
}

// ---------------------------------------------------------------------------

extern "C" void kernel_launch(void* const* d_in, const int* in_sizes, int n_in,
                              void* d_out, int out_size)
{
    const float* x  = (const float*)d_in[0];
    const float* wq = (const float*)d_in[1];
    const float* wk = (const float*)d_in[2];
    const float* wv = (const float*)d_in[3];
    const float* wo = (const float*)d_in[4];
    float* out = (float*)d_out;

    __half *qh, *kh, *vh, *atth, *xh, *wqh, *wkh, *wvh, *woh;
    cudaGetSymbolAddress((void**)&qh,   g_qh);
    cudaGetSymbolAddress((void**)&kh,   g_kh);
    cudaGetSymbolAddress((void**)&vh,   g_vh);
    cudaGetSymbolAddress((void**)&atth, g_atth);
    cudaGetSymbolAddress((void**)&xh,   g_xh);
    cudaGetSymbolAddress((void**)&wqh,  g_wqh);
    cudaGetSymbolAddress((void**)&wkh,  g_wkh);
    cudaGetSymbolAddress((void**)&wvh,  g_wvh);
    cudaGetSymbolAddress((void**)&woh,  g_woh);

    convert_all_kernel<<<2048, 256>>>(x, wq, wk, wv, wo,
                                      xh, wqh, wkh, wvh, woh);

    cudaFuncSetAttribute(gemm_nt_f16_kernel<__half>,
                         cudaFuncAttributeMaxDynamicSharedMemorySize, GSM3);
    cudaFuncSetAttribute(gemm_nt_f16_kernel<float>,
                         cudaFuncAttributeMaxDynamicSharedMemorySize, GSM3);

    // Fused QKV projection: z selects weight/output
    dim3 gq(D_ / 128, NT_ / 128, 3);  // (8, 32, 3)
    gemm_nt_f16_kernel<__half><<<gq, 256, GSM3>>>(
        xh, wqh, wkh, wvh, qh, kh, vh, NT_, D_, D_);

    // Paired attention: 8x16x2 = 256 blocks, uniform 34 KV tiles each
    dim3 ga(NQT / 2, H_, B_);         // (8, 16, 2)
    attn_f16_kernel<<<ga, 256>>>(qh, kh, vh, atth);

    dim3 gg(D_ / 128, NT_ / 128, 1);
    gemm_nt_f16_kernel<float><<<gg, 256, GSM3>>>(
        atth, woh, woh, woh, out, out, out, NT_, D_, D_);
}

// round 16
// speedup vs baseline: 1.1594x; 1.0189x over previous
#include <cuda_runtime.h>
#include <cuda_fp16.h>
#include <stdint.h>
#include <math.h>

#define B_   2
#define S_   2048
#define D_   1024
#define H_   16
#define DH_  64
#define NT_  (B_ * S_)          // 4096 tokens
#define NQT  (S_ / 128)         // 16 q-tiles

// Scratch (allocation-free rule -> __device__ globals)
__device__ __half g_qh[NT_ * D_];
__device__ __half g_kh[NT_ * D_];
__device__ __half g_vh[NT_ * D_];
__device__ __half g_atth[NT_ * D_];
__device__ __half g_xh[NT_ * D_];
__device__ __half g_wqh[D_ * D_];
__device__ __half g_wkh[D_ * D_];
__device__ __half g_wvh[D_ * D_];
__device__ __half g_woh[D_ * D_];

__device__ __forceinline__ void mma16816(float* c, const uint32_t* a,
                                         uint32_t b0, uint32_t b1)
{
    asm volatile(
        "mma.sync.aligned.m16n8k16.row.col.f32.f16.f16.f32 "
        "{%0,%1,%2,%3}, {%4,%5,%6,%7}, {%8,%9}, {%0,%1,%2,%3};\n"
        : "+f"(c[0]), "+f"(c[1]), "+f"(c[2]), "+f"(c[3])
        : "r"(a[0]), "r"(a[1]), "r"(a[2]), "r"(a[3]), "r"(b0), "r"(b1));
}

__device__ __forceinline__ void ldsm4(uint32_t* r, const void* p)
{
    uint32_t a = (uint32_t)__cvta_generic_to_shared(p);
    asm volatile("ldmatrix.sync.aligned.m8n8.x4.shared.b16 {%0,%1,%2,%3}, [%4];"
                 : "=r"(r[0]), "=r"(r[1]), "=r"(r[2]), "=r"(r[3]) : "r"(a));
}

__device__ __forceinline__ void cp16(void* smem, const void* gmem)
{
    uint32_t sa = (uint32_t)__cvta_generic_to_shared(smem);
    asm volatile("cp.async.cg.shared.global [%0], [%1], 16;\n"
                 :: "r"(sa), "l"(gmem));
}
__device__ __forceinline__ void cp_commit()
{
    asm volatile("cp.async.commit_group;\n");
}

__device__ __forceinline__ uint32_t ex2_f16x2(float d0, float d1)
{
    __half2 h = __floats2half2_rn(d0, d1);
    uint32_t hp = *(uint32_t*)&h, p;
    asm("ex2.approx.f16x2 %0, %1;" : "=r"(p) : "r"(hp));
    return p;
}

// ---------------------------------------------------------------------------
// Fused fp32 -> fp16 convert for x + 4 weights (8M elements total).
// ---------------------------------------------------------------------------
__global__ __launch_bounds__(256) void convert_all_kernel(
    const float* __restrict__ x,  const float* __restrict__ wq,
    const float* __restrict__ wk, const float* __restrict__ wv,
    const float* __restrict__ wo,
    __half* __restrict__ xh, __half* __restrict__ wqh,
    __half* __restrict__ wkh, __half* __restrict__ wvh,
    __half* __restrict__ woh)
{
    size_t gi = ((size_t)blockIdx.x * 256 + threadIdx.x) * 16;
    int seg = (int)(gi >> 20);
    const float* in; __half* out; size_t off;
    if (seg < 4)      { in = x;  out = xh;  off = gi; }
    else if (seg == 4){ in = wq; out = wqh; off = gi - (4u << 20); }
    else if (seg == 5){ in = wk; out = wkh; off = gi - (5u << 20); }
    else if (seg == 6){ in = wv; out = wvh; off = gi - (6u << 20); }
    else              { in = wo; out = woh; off = gi - (7u << 20); }

    float4 v0 = *(const float4*)&in[off];
    float4 v1 = *(const float4*)&in[off + 4];
    float4 v2 = *(const float4*)&in[off + 8];
    float4 v3 = *(const float4*)&in[off + 12];
    __half2 h[8];
    h[0] = __floats2half2_rn(v0.x, v0.y); h[1] = __floats2half2_rn(v0.z, v0.w);
    h[2] = __floats2half2_rn(v1.x, v1.y); h[3] = __floats2half2_rn(v1.z, v1.w);
    h[4] = __floats2half2_rn(v2.x, v2.y); h[5] = __floats2half2_rn(v2.z, v2.w);
    h[6] = __floats2half2_rn(v3.x, v3.y); h[7] = __floats2half2_rn(v3.z, v3.w);
    *(int4*)&out[off]     = *(int4*)&h[0];
    *(int4*)&out[off + 8] = *(int4*)&h[4];
}

// ---------------------------------------------------------------------------
// C[M,N] = A[M,K] @ W[N,K]^T  fp16 mma, f32 accum, OutT epilogue.
// Block 128x128, BK=64, 8 warps (2x4), warp tile 64x32 (4x4 mma grid).
// 3-stage cp.async ring, ONE syncthreads per slab, ldmatrix fragments.
// blockIdx.z picks W/C pair (QKV fuse). PDL gridsync at entry.
// ---------------------------------------------------------------------------
#define LDG3 72                      // pitch in halves (144 B)
#define GT3  (128 * LDG3)            // halves per operand tile
#define GSM3 (3 * 2 * GT3 * 2)       // bytes: 3 stages x (A+B) x 2B = 110592

template <typename OutT>
__global__ __launch_bounds__(256, 2) void gemm_nt_f16_kernel(
    const __half* __restrict__ A,
    const __half* __restrict__ W0, const __half* __restrict__ W1,
    const __half* __restrict__ W2,
    OutT* __restrict__ C0, OutT* __restrict__ C1, OutT* __restrict__ C2,
    int M, int N, int K)
{
    extern __shared__ __half smem[];
    const __half* W = (blockIdx.z == 0) ? W0 : (blockIdx.z == 1) ? W1 : W2;
    OutT*         C = (blockIdx.z == 0) ? C0 : (blockIdx.z == 1) ? C1 : C2;

    int tid  = threadIdx.x;
    int wid  = tid >> 5, lane = tid & 31;
    int gid  = lane >> 2, tig = lane & 3;
    int wm   = (wid & 1) * 64;
    int wn   = (wid >> 1) * 32;
    int m0   = blockIdx.y * 128;
    int n0   = blockIdx.x * 128;

    int aoff = (wm + (lane & 15)) * LDG3 + (lane >> 4) * 8;
    int boff = (wn + (lane & 7) + ((lane >> 4) & 1) * 8) * LDG3
             + ((lane >> 3) & 1) * 8;

    float acc[4][4][4] = {};

    const int NIT = K / 64;          // 16

    auto load_stage = [&](int slot, int k0) {
        __half* as = smem + slot * 2 * GT3;
        __half* bs = as + GT3;
        #pragma unroll
        for (int u = 0; u < 4; u++) {
            int c = tid + u * 256;              // 0..1023
            int row = c >> 3, col = (c & 7) * 8;
            cp16(&as[row * LDG3 + col], &A[(size_t)(m0 + row) * K + k0 + col]);
            cp16(&bs[row * LDG3 + col], &W[(size_t)(n0 + row) * K + k0 + col]);
        }
        cp_commit();
    };

    // PDL: wait for predecessor's data before first read
    cudaGridDependencySynchronize();

    load_stage(0, 0);
    load_stage(1, 64);

    for (int t = 0; t < NIT; t++) {
        if (t + 1 < NIT) asm volatile("cp.async.wait_group 1;\n");
        else             asm volatile("cp.async.wait_group 0;\n");
        __syncthreads();

        if (t + 2 < NIT) load_stage((t + 2) % 3, (t + 2) * 64);

        const __half* as = smem + (t % 3) * 2 * GT3;
        const __half* bs = as + GT3;

        #pragma unroll
        for (int ks = 0; ks < 4; ks++) {
            int kb = ks * 16;
            uint32_t af[4][4], bf[2][4];
            #pragma unroll
            for (int i = 0; i < 4; i++)
                ldsm4(af[i], as + aoff + i * 16 * LDG3 + kb);
            #pragma unroll
            for (int jp = 0; jp < 2; jp++)
                ldsm4(bf[jp], bs + boff + jp * 16 * LDG3 + kb);
            #pragma unroll
            for (int i = 0; i < 4; i++) {
                mma16816(acc[i][0], af[i], bf[0][0], bf[0][1]);
                mma16816(acc[i][1], af[i], bf[0][2], bf[0][3]);
                mma16816(acc[i][2], af[i], bf[1][0], bf[1][1]);
                mma16816(acc[i][3], af[i], bf[1][2], bf[1][3]);
            }
        }
    }

    #pragma unroll
    for (int i = 0; i < 4; i++)
        #pragma unroll
        for (int j = 0; j < 4; j++) {
            int r = m0 + wm + i * 16 + gid;
            int c = n0 + wn + j * 8 + tig * 2;
            if (sizeof(OutT) == 2) {
                *(__half2*)((__half*)C + (size_t)r * N + c) =
                    __floats2half2_rn(acc[i][j][0], acc[i][j][1]);
                *(__half2*)((__half*)C + (size_t)(r + 8) * N + c) =
                    __floats2half2_rn(acc[i][j][2], acc[i][j][3]);
            } else {
                float2 lo = {acc[i][j][0], acc[i][j][1]};
                float2 hi = {acc[i][j][2], acc[i][j][3]};
                *(float2*)((float*)C + (size_t)r * N + c)       = lo;
                *(float2*)((float*)C + (size_t)(r + 8) * N + c) = hi;
            }
        }
}

// ---------------------------------------------------------------------------
// Causal flash attention, fp16 tensor cores (FA2 register-resident),
// 3-stage cp.async KV ring (ONE sync/tile), ldmatrix K fragments,
// f16x2 softmax exp, fully-masked warp-tiles skipped.
// PAIRED SCHEDULE: block p handles q-tiles p and NQT-1-p (34 KV tiles each).
// ---------------------------------------------------------------------------
#define LKV 72

__global__ __launch_bounds__(256, 2) void attn_f16_kernel(
    const __half* __restrict__ qh, const __half* __restrict__ kh,
    const __half* __restrict__ vh, __half* __restrict__ oh)
{
    __shared__ __half Ks[3][64 * LKV];
    __shared__ __half Vs[3][64 * LKV];

    int tid = threadIdx.x, wid = tid >> 5, lane = tid & 31;
    int gid = lane >> 2, tig = lane & 3;
    int h  = blockIdx.y, b = blockIdx.z;
    size_t base = ((size_t)b * S_) * D_ + h * DH_;
    int wrow = wid * 16;

    const __half* qb = qh + base;
    const __half* kb = kh + base;
    const __half* vb = vh + base;
    __half* ob = oh + base;

    int lrow = tid >> 3, loff = (tid & 7) * 8;
    int kfoff = ((lane & 7) + ((lane >> 4) & 1) * 8) * LKV
              + ((lane >> 3) & 1) * 8;
    const float c2 = 0.125f * 1.44269504f;   // scale * log2(e)

    // PDL: q/k/v come from the QKV projection kernel
    cudaGridDependencySynchronize();

    #pragma unroll 1
    for (int sub = 0; sub < 2; sub++) {
        int qt = (sub == 0) ? (int)blockIdx.x : (NQT - 1 - (int)blockIdx.x);
        int q0 = qt * 128;
        int row0 = q0 + wrow + gid;

        uint32_t qf[4][4];
        #pragma unroll
        for (int kc = 0; kc < 4; kc++) {
            const __half* p0 = &qb[(size_t)row0 * D_ + kc * 16 + tig * 2];
            const __half* p1 = &qb[(size_t)(row0 + 8) * D_ + kc * 16 + tig * 2];
            qf[kc][0] = *(const uint32_t*)(p0);
            qf[kc][1] = *(const uint32_t*)(p1);
            qf[kc][2] = *(const uint32_t*)(p0 + 8);
            qf[kc][3] = *(const uint32_t*)(p1 + 8);
        }

        float m0r = -1e30f, m1r = -1e30f, l0r = 0.0f, l1r = 0.0f;
        float oacc[8][4] = {};

        int ntiles = (q0 >> 6) + 2;

        // prologue: tiles 0,1 -> slots 0,1
        #pragma unroll
        for (int s = 0; s < 2; s++) {
            int kv = s * 64;
            #pragma unroll
            for (int u = 0; u < 2; u++) {
                int row = lrow + u * 32;
                cp16(&Ks[s][row * LKV + loff], &kb[(size_t)(kv + row) * D_ + loff]);
                cp16(&Vs[s][row * LKV + loff], &vb[(size_t)(kv + row) * D_ + loff]);
            }
            cp_commit();
        }

        for (int kt = 0; kt < ntiles; kt++) {
            int kv0 = kt * 64;
            int sl = kt % 3;
            if (kt + 1 < ntiles) asm volatile("cp.async.wait_group 1;\n");
            else                 asm volatile("cp.async.wait_group 0;\n");
            __syncthreads();

            // prefetch tile kt+2 into slot (kt+2)%3 (its readers done pre-sync)
            if (kt + 2 < ntiles) {
                int nv0 = (kt + 2) * 64;
                int ps = (kt + 2) % 3;
                #pragma unroll
                for (int u = 0; u < 2; u++) {
                    int row = lrow + u * 32;
                    cp16(&Ks[ps][row * LKV + loff],
                         &kb[(size_t)(nv0 + row) * D_ + loff]);
                    cp16(&Vs[ps][row * LKV + loff],
                         &vb[(size_t)(nv0 + row) * D_ + loff]);
                }
                cp_commit();
            }

            // skip fully-masked warp-tiles (warp-uniform)
            bool active = (kv0 <= q0 + wrow + 15);
            if (active) {
                // S = Q K^T (raw scores)
                float sacc[8][4] = {};
                #pragma unroll
                for (int kc = 0; kc < 4; kc++) {
                    #pragma unroll
                    for (int j2 = 0; j2 < 4; j2++) {
                        uint32_t bf[4];
                        ldsm4(bf, &Ks[sl][j2 * 16 * LKV + kfoff + kc * 16]);
                        mma16816(sacc[2 * j2],     qf[kc], bf[0], bf[1]);
                        mma16816(sacc[2 * j2 + 1], qf[kc], bf[2], bf[3]);
                    }
                }

                bool need_mask = (kv0 + 63 > q0 + wrow);
                if (need_mask) {
                    #pragma unroll
                    for (int j = 0; j < 8; j++) {
                        int c0 = kv0 + j * 8 + tig * 2;
                        if (c0     > row0)     sacc[j][0] = -1e30f;
                        if (c0 + 1 > row0)     sacc[j][1] = -1e30f;
                        if (c0     > row0 + 8) sacc[j][2] = -1e30f;
                        if (c0 + 1 > row0 + 8) sacc[j][3] = -1e30f;
                    }
                }

                float rm0 = -1e30f, rm1 = -1e30f;
                #pragma unroll
                for (int j = 0; j < 8; j++) {
                    rm0 = fmaxf(rm0, fmaxf(sacc[j][0], sacc[j][1]));
                    rm1 = fmaxf(rm1, fmaxf(sacc[j][2], sacc[j][3]));
                }
                rm0 = fmaxf(rm0, __shfl_xor_sync(0xffffffffu, rm0, 1));
                rm0 = fmaxf(rm0, __shfl_xor_sync(0xffffffffu, rm0, 2));
                rm1 = fmaxf(rm1, __shfl_xor_sync(0xffffffffu, rm1, 1));
                rm1 = fmaxf(rm1, __shfl_xor_sync(0xffffffffu, rm1, 2));
                float nm0 = fmaxf(m0r, rm0), nm1 = fmaxf(m1r, rm1);
                float corr0 = exp2f((m0r - nm0) * c2);
                float corr1 = exp2f((m1r - nm1) * c2);
                m0r = nm0; m1r = nm1;
                float nc0 = nm0 * c2, nc1 = nm1 * c2;

                uint32_t ph[8][2];
                float sum0 = 0.0f, sum1 = 0.0f;
                #pragma unroll
                for (int j = 0; j < 8; j++) {
                    float d0 = fmaf(sacc[j][0], c2, -nc0);
                    float d1 = fmaf(sacc[j][1], c2, -nc0);
                    float d2 = fmaf(sacc[j][2], c2, -nc1);
                    float d3 = fmaf(sacc[j][3], c2, -nc1);
                    ph[j][0] = ex2_f16x2(d0, d1);
                    ph[j][1] = ex2_f16x2(d2, d3);
                    float2 f01 = __half22float2(*(__half2*)&ph[j][0]);
                    float2 f23 = __half22float2(*(__half2*)&ph[j][1]);
                    sum0 += f01.x + f01.y;
                    sum1 += f23.x + f23.y;
                }
                sum0 += __shfl_xor_sync(0xffffffffu, sum0, 1);
                sum0 += __shfl_xor_sync(0xffffffffu, sum0, 2);
                sum1 += __shfl_xor_sync(0xffffffffu, sum1, 1);
                sum1 += __shfl_xor_sync(0xffffffffu, sum1, 2);
                l0r = l0r * corr0 + sum0;
                l1r = l1r * corr1 + sum1;

                #pragma unroll
                for (int j = 0; j < 8; j++) {
                    oacc[j][0] *= corr0; oacc[j][1] *= corr0;
                    oacc[j][2] *= corr1; oacc[j][3] *= corr1;
                }

                int mi = lane >> 3, rr = lane & 7;
                #pragma unroll
                for (int kc = 0; kc < 4; kc++) {
                    uint32_t pf[4];
                    pf[0] = ph[2 * kc][0];
                    pf[1] = ph[2 * kc][1];
                    pf[2] = ph[2 * kc + 1][0];
                    pf[3] = ph[2 * kc + 1][1];

                    #pragma unroll
                    for (int jop = 0; jop < 4; jop++) {
                        uint32_t r0, r1, r2, r3;
                        const __half* vp = &Vs[sl][(kc * 16 + (mi & 1) * 8 + rr) * LKV
                                                   + jop * 16 + (mi >> 1) * 8];
                        uint32_t va = (uint32_t)__cvta_generic_to_shared(vp);
                        asm volatile(
                            "ldmatrix.sync.aligned.m8n8.x4.trans.shared.b16 "
                            "{%0,%1,%2,%3}, [%4];"
                            : "=r"(r0), "=r"(r1), "=r"(r2), "=r"(r3) : "r"(va));
                        mma16816(oacc[2 * jop],     pf, r0, r1);
                        mma16816(oacc[2 * jop + 1], pf, r2, r3);
                    }
                }
            }
        }

        // all warps done with smem before sub1 re-uses slots
        __syncthreads();

        float inv0 = 1.0f / l0r, inv1 = 1.0f / l1r;
        #pragma unroll
        for (int j = 0; j < 8; j++) {
            int c = j * 8 + tig * 2;
            *(__half2*)&ob[(size_t)row0 * D_ + c] =
                __floats2half2_rn(oacc[j][0] * inv0, oacc[j][1] * inv0);
            *(__half2*)&ob[(size_t)(row0 + 8) * D_ + c] =
                __floats2half2_rn(oacc[j][2] * inv1, oacc[j][3] * inv1);
        }
    }
}

// ---------------------------------------------------------------------------

extern "C" void kernel_launch(void* const* d_in, const int* in_sizes, int n_in,
                              void* d_out, int out_size)
{
    const float* x  = (const float*)d_in[0];
    const float* wq = (const float*)d_in[1];
    const float* wk = (const float*)d_in[2];
    const float* wv = (const float*)d_in[3];
    const float* wo = (const float*)d_in[4];
    float* out = (float*)d_out;

    __half *qh, *kh, *vh, *atth, *xh, *wqh, *wkh, *wvh, *woh;
    cudaGetSymbolAddress((void**)&qh,   g_qh);
    cudaGetSymbolAddress((void**)&kh,   g_kh);
    cudaGetSymbolAddress((void**)&vh,   g_vh);
    cudaGetSymbolAddress((void**)&atth, g_atth);
    cudaGetSymbolAddress((void**)&xh,   g_xh);
    cudaGetSymbolAddress((void**)&wqh,  g_wqh);
    cudaGetSymbolAddress((void**)&wkh,  g_wkh);
    cudaGetSymbolAddress((void**)&wvh,  g_wvh);
    cudaGetSymbolAddress((void**)&woh,  g_woh);

    convert_all_kernel<<<2048, 256>>>(x, wq, wk, wv, wo,
                                      xh, wqh, wkh, wvh, woh);

    cudaFuncSetAttribute(gemm_nt_f16_kernel<__half>,
                         cudaFuncAttributeMaxDynamicSharedMemorySize, GSM3);
    cudaFuncSetAttribute(gemm_nt_f16_kernel<float>,
                         cudaFuncAttributeMaxDynamicSharedMemorySize, GSM3);

    cudaLaunchAttribute pdl[1];
    pdl[0].id = cudaLaunchAttributeProgrammaticStreamSerialization;
    pdl[0].val.programmaticStreamSerializationAllowed = 1;

    // Fused QKV projection (PDL after convert)
    {
        cudaLaunchConfig_t cfg = {};
        cfg.gridDim  = dim3(D_ / 128, NT_ / 128, 3);
        cfg.blockDim = dim3(256, 1, 1);
        cfg.dynamicSmemBytes = GSM3;
        cfg.attrs = pdl; cfg.numAttrs = 1;
        cudaLaunchKernelEx(&cfg, gemm_nt_f16_kernel<__half>,
                           (const __half*)xh,
                           (const __half*)wqh, (const __half*)wkh,
                           (const __half*)wvh,
                           qh, kh, vh, (int)NT_, (int)D_, (int)D_);
    }

    // Paired attention (PDL after QKV)
    {
        cudaLaunchConfig_t cfg = {};
        cfg.gridDim  = dim3(NQT / 2, H_, B_);
        cfg.blockDim = dim3(256, 1, 1);
        cfg.dynamicSmemBytes = 0;
        cfg.attrs = pdl; cfg.numAttrs = 1;
        cudaLaunchKernelEx(&cfg, attn_f16_kernel,
                           (const __half*)qh, (const __half*)kh,
                           (const __half*)vh, atth);
    }

    // Output projection (PDL after attention)
    {
        cudaLaunchConfig_t cfg = {};
        cfg.gridDim  = dim3(D_ / 128, NT_ / 128, 1);
        cfg.blockDim = dim3(256, 1, 1);
        cfg.dynamicSmemBytes = GSM3;
        cfg.attrs = pdl; cfg.numAttrs = 1;
        cudaLaunchKernelEx(&cfg, gemm_nt_f16_kernel<float>,
                           (const __half*)atth,
                           (const __half*)woh, (const __half*)woh,
                           (const __half*)woh,
                           out, out, out, (int)NT_, (int)D_, (int)D_);
    }
}

// round 17
// speedup vs baseline: 1.1745x; 1.0130x over previous
#include <cuda_runtime.h>
#include <cuda_fp16.h>
#include <stdint.h>
#include <math.h>

#define B_   2
#define S_   2048
#define D_   1024
#define H_   16
#define DH_  64
#define NT_  (B_ * S_)          // 4096 tokens
#define NQT  (S_ / 128)         // 16 q-tiles

// Scratch (allocation-free rule -> __device__ globals)
__device__ __half g_qh[NT_ * D_];
__device__ __half g_kh[NT_ * D_];
__device__ __half g_vh[NT_ * D_];
__device__ __half g_atth[NT_ * D_];
__device__ __half g_xh[NT_ * D_];
__device__ __half g_wqh[D_ * D_];
__device__ __half g_wkh[D_ * D_];
__device__ __half g_wvh[D_ * D_];
__device__ __half g_woh[D_ * D_];

__device__ __forceinline__ void mma16816(float* c, const uint32_t* a,
                                         uint32_t b0, uint32_t b1)
{
    asm volatile(
        "mma.sync.aligned.m16n8k16.row.col.f32.f16.f16.f32 "
        "{%0,%1,%2,%3}, {%4,%5,%6,%7}, {%8,%9}, {%0,%1,%2,%3};\n"
        : "+f"(c[0]), "+f"(c[1]), "+f"(c[2]), "+f"(c[3])
        : "r"(a[0]), "r"(a[1]), "r"(a[2]), "r"(a[3]), "r"(b0), "r"(b1));
}

__device__ __forceinline__ void ldsm4(uint32_t* r, const void* p)
{
    uint32_t a = (uint32_t)__cvta_generic_to_shared(p);
    asm volatile("ldmatrix.sync.aligned.m8n8.x4.shared.b16 {%0,%1,%2,%3}, [%4];"
                 : "=r"(r[0]), "=r"(r[1]), "=r"(r[2]), "=r"(r[3]) : "r"(a));
}

__device__ __forceinline__ void cp16(void* smem, const void* gmem)
{
    uint32_t sa = (uint32_t)__cvta_generic_to_shared(smem);
    asm volatile("cp.async.cg.shared.global [%0], [%1], 16;\n"
                 :: "r"(sa), "l"(gmem));
}
__device__ __forceinline__ void cp_commit()
{
    asm volatile("cp.async.commit_group;\n");
}

__device__ __forceinline__ uint32_t ex2_f16x2(float d0, float d1)
{
    __half2 h = __floats2half2_rn(d0, d1);
    uint32_t hp = *(uint32_t*)&h, p;
    asm("ex2.approx.f16x2 %0, %1;" : "=r"(p) : "r"(hp));
    return p;
}

// ---------------------------------------------------------------------------
// Fused fp32 -> fp16 convert for x + 4 weights (8M elements total).
// ---------------------------------------------------------------------------
__global__ __launch_bounds__(256) void convert_all_kernel(
    const float* __restrict__ x,  const float* __restrict__ wq,
    const float* __restrict__ wk, const float* __restrict__ wv,
    const float* __restrict__ wo,
    __half* __restrict__ xh, __half* __restrict__ wqh,
    __half* __restrict__ wkh, __half* __restrict__ wvh,
    __half* __restrict__ woh)
{
    size_t gi = ((size_t)blockIdx.x * 256 + threadIdx.x) * 16;
    int seg = (int)(gi >> 20);
    const float* in; __half* out; size_t off;
    if (seg < 4)      { in = x;  out = xh;  off = gi; }
    else if (seg == 4){ in = wq; out = wqh; off = gi - (4u << 20); }
    else if (seg == 5){ in = wk; out = wkh; off = gi - (5u << 20); }
    else if (seg == 6){ in = wv; out = wvh; off = gi - (6u << 20); }
    else              { in = wo; out = woh; off = gi - (7u << 20); }

    float4 v0 = *(const float4*)&in[off];
    float4 v1 = *(const float4*)&in[off + 4];
    float4 v2 = *(const float4*)&in[off + 8];
    float4 v3 = *(const float4*)&in[off + 12];
    __half2 h[8];
    h[0] = __floats2half2_rn(v0.x, v0.y); h[1] = __floats2half2_rn(v0.z, v0.w);
    h[2] = __floats2half2_rn(v1.x, v1.y); h[3] = __floats2half2_rn(v1.z, v1.w);
    h[4] = __floats2half2_rn(v2.x, v2.y); h[5] = __floats2half2_rn(v2.z, v2.w);
    h[6] = __floats2half2_rn(v3.x, v3.y); h[7] = __floats2half2_rn(v3.z, v3.w);
    *(int4*)&out[off]     = *(int4*)&h[0];
    *(int4*)&out[off + 8] = *(int4*)&h[4];
}

// ---------------------------------------------------------------------------
// C[M,N] = A[M,K] @ W[N,K]^T  fp16 mma, f32 accum, OutT epilogue.
// Block 128x128, BK=64, 8 warps (2x4), warp tile 64x32 (4x4 mma grid).
// 3-stage cp.async ring, ONE syncthreads per slab, ldmatrix fragments.
// blockIdx.z picks W/C pair (QKV fuse). PDL gridsync at entry. (Frozen.)
// ---------------------------------------------------------------------------
#define LDG3 72                      // pitch in halves (144 B)
#define GT3  (128 * LDG3)            // halves per operand tile
#define GSM3 (3 * 2 * GT3 * 2)       // bytes: 3 stages x (A+B) x 2B = 110592

template <typename OutT>
__global__ __launch_bounds__(256, 2) void gemm_nt_f16_kernel(
    const __half* __restrict__ A,
    const __half* __restrict__ W0, const __half* __restrict__ W1,
    const __half* __restrict__ W2,
    OutT* __restrict__ C0, OutT* __restrict__ C1, OutT* __restrict__ C2,
    int M, int N, int K)
{
    extern __shared__ __half smem[];
    const __half* W = (blockIdx.z == 0) ? W0 : (blockIdx.z == 1) ? W1 : W2;
    OutT*         C = (blockIdx.z == 0) ? C0 : (blockIdx.z == 1) ? C1 : C2;

    int tid  = threadIdx.x;
    int wid  = tid >> 5, lane = tid & 31;
    int gid  = lane >> 2, tig = lane & 3;
    int wm   = (wid & 1) * 64;
    int wn   = (wid >> 1) * 32;
    int m0   = blockIdx.y * 128;
    int n0   = blockIdx.x * 128;

    int aoff = (wm + (lane & 15)) * LDG3 + (lane >> 4) * 8;
    int boff = (wn + (lane & 7) + ((lane >> 4) & 1) * 8) * LDG3
             + ((lane >> 3) & 1) * 8;

    float acc[4][4][4] = {};

    const int NIT = K / 64;          // 16

    auto load_stage = [&](int slot, int k0) {
        __half* as = smem + slot * 2 * GT3;
        __half* bs = as + GT3;
        #pragma unroll
        for (int u = 0; u < 4; u++) {
            int c = tid + u * 256;              // 0..1023
            int row = c >> 3, col = (c & 7) * 8;
            cp16(&as[row * LDG3 + col], &A[(size_t)(m0 + row) * K + k0 + col]);
            cp16(&bs[row * LDG3 + col], &W[(size_t)(n0 + row) * K + k0 + col]);
        }
        cp_commit();
    };

    cudaGridDependencySynchronize();

    load_stage(0, 0);
    load_stage(1, 64);

    for (int t = 0; t < NIT; t++) {
        if (t + 1 < NIT) asm volatile("cp.async.wait_group 1;\n");
        else             asm volatile("cp.async.wait_group 0;\n");
        __syncthreads();

        if (t + 2 < NIT) load_stage((t + 2) % 3, (t + 2) * 64);

        const __half* as = smem + (t % 3) * 2 * GT3;
        const __half* bs = as + GT3;

        #pragma unroll
        for (int ks = 0; ks < 4; ks++) {
            int kb = ks * 16;
            uint32_t af[4][4], bf[2][4];
            #pragma unroll
            for (int i = 0; i < 4; i++)
                ldsm4(af[i], as + aoff + i * 16 * LDG3 + kb);
            #pragma unroll
            for (int jp = 0; jp < 2; jp++)
                ldsm4(bf[jp], bs + boff + jp * 16 * LDG3 + kb);
            #pragma unroll
            for (int i = 0; i < 4; i++) {
                mma16816(acc[i][0], af[i], bf[0][0], bf[0][1]);
                mma16816(acc[i][1], af[i], bf[0][2], bf[0][3]);
                mma16816(acc[i][2], af[i], bf[1][0], bf[1][1]);
                mma16816(acc[i][3], af[i], bf[1][2], bf[1][3]);
            }
        }
    }

    #pragma unroll
    for (int i = 0; i < 4; i++)
        #pragma unroll
        for (int j = 0; j < 4; j++) {
            int r = m0 + wm + i * 16 + gid;
            int c = n0 + wn + j * 8 + tig * 2;
            if (sizeof(OutT) == 2) {
                *(__half2*)((__half*)C + (size_t)r * N + c) =
                    __floats2half2_rn(acc[i][j][0], acc[i][j][1]);
                *(__half2*)((__half*)C + (size_t)(r + 8) * N + c) =
                    __floats2half2_rn(acc[i][j][2], acc[i][j][3]);
            } else {
                float2 lo = {acc[i][j][0], acc[i][j][1]};
                float2 hi = {acc[i][j][2], acc[i][j][3]};
                *(float2*)((float*)C + (size_t)r * N + c)       = lo;
                *(float2*)((float*)C + (size_t)(r + 8) * N + c) = hi;
            }
        }
}

// ---------------------------------------------------------------------------
// Causal flash attention, fp16 tensor cores (FA2 register-resident),
// 3-stage cp.async KV ring (ONE sync/tile), ldmatrix K fragments,
// f16x2 softmax exp, row-sums via ones-MMA (no sum shuffles/unpacks),
// fully-masked warp-tiles skipped.
// PAIRED SCHEDULE: block p handles q-tiles p and NQT-1-p (34 KV tiles each).
// ---------------------------------------------------------------------------
#define LKV 72
#define ONES16 0x3C003C00u   // (1.0h, 1.0h)

__global__ __launch_bounds__(256, 2) void attn_f16_kernel(
    const __half* __restrict__ qh, const __half* __restrict__ kh,
    const __half* __restrict__ vh, __half* __restrict__ oh)
{
    __shared__ __half Ks[3][64 * LKV];
    __shared__ __half Vs[3][64 * LKV];

    int tid = threadIdx.x, wid = tid >> 5, lane = tid & 31;
    int gid = lane >> 2, tig = lane & 3;
    int h  = blockIdx.y, b = blockIdx.z;
    size_t base = ((size_t)b * S_) * D_ + h * DH_;
    int wrow = wid * 16;

    const __half* qb = qh + base;
    const __half* kb = kh + base;
    const __half* vb = vh + base;
    __half* ob = oh + base;

    int lrow = tid >> 3, loff = (tid & 7) * 8;
    int kfoff = ((lane & 7) + ((lane >> 4) & 1) * 8) * LKV
              + ((lane >> 3) & 1) * 8;
    const float c2 = 0.125f * 1.44269504f;   // scale * log2(e)

    cudaGridDependencySynchronize();

    #pragma unroll 1
    for (int sub = 0; sub < 2; sub++) {
        int qt = (sub == 0) ? (int)blockIdx.x : (NQT - 1 - (int)blockIdx.x);
        int q0 = qt * 128;
        int row0 = q0 + wrow + gid;

        uint32_t qf[4][4];
        #pragma unroll
        for (int kc = 0; kc < 4; kc++) {
            const __half* p0 = &qb[(size_t)row0 * D_ + kc * 16 + tig * 2];
            const __half* p1 = &qb[(size_t)(row0 + 8) * D_ + kc * 16 + tig * 2];
            qf[kc][0] = *(const uint32_t*)(p0);
            qf[kc][1] = *(const uint32_t*)(p1);
            qf[kc][2] = *(const uint32_t*)(p0 + 8);
            qf[kc][3] = *(const uint32_t*)(p1 + 8);
        }

        float m0r = -1e30f, m1r = -1e30f;
        float oacc[8][4] = {};
        float lsum[4] = {};      // row-sum accumulator via ones-MMA

        int ntiles = (q0 >> 6) + 2;

        // prologue: tiles 0,1 -> slots 0,1
        #pragma unroll
        for (int s = 0; s < 2; s++) {
            int kv = s * 64;
            #pragma unroll
            for (int u = 0; u < 2; u++) {
                int row = lrow + u * 32;
                cp16(&Ks[s][row * LKV + loff], &kb[(size_t)(kv + row) * D_ + loff]);
                cp16(&Vs[s][row * LKV + loff], &vb[(size_t)(kv + row) * D_ + loff]);
            }
            cp_commit();
        }

        for (int kt = 0; kt < ntiles; kt++) {
            int kv0 = kt * 64;
            int sl = kt % 3;
            if (kt + 1 < ntiles) asm volatile("cp.async.wait_group 1;\n");
            else                 asm volatile("cp.async.wait_group 0;\n");
            __syncthreads();

            if (kt + 2 < ntiles) {
                int nv0 = (kt + 2) * 64;
                int ps = (kt + 2) % 3;
                #pragma unroll
                for (int u = 0; u < 2; u++) {
                    int row = lrow + u * 32;
                    cp16(&Ks[ps][row * LKV + loff],
                         &kb[(size_t)(nv0 + row) * D_ + loff]);
                    cp16(&Vs[ps][row * LKV + loff],
                         &vb[(size_t)(nv0 + row) * D_ + loff]);
                }
                cp_commit();
            }

            bool active = (kv0 <= q0 + wrow + 15);
            if (active) {
                float sacc[8][4] = {};
                #pragma unroll
                for (int kc = 0; kc < 4; kc++) {
                    #pragma unroll
                    for (int j2 = 0; j2 < 4; j2++) {
                        uint32_t bf[4];
                        ldsm4(bf, &Ks[sl][j2 * 16 * LKV + kfoff + kc * 16]);
                        mma16816(sacc[2 * j2],     qf[kc], bf[0], bf[1]);
                        mma16816(sacc[2 * j2 + 1], qf[kc], bf[2], bf[3]);
                    }
                }

                bool need_mask = (kv0 + 63 > q0 + wrow);
                if (need_mask) {
                    #pragma unroll
                    for (int j = 0; j < 8; j++) {
                        int c0 = kv0 + j * 8 + tig * 2;
                        if (c0     > row0)     sacc[j][0] = -1e30f;
                        if (c0 + 1 > row0)     sacc[j][1] = -1e30f;
                        if (c0     > row0 + 8) sacc[j][2] = -1e30f;
                        if (c0 + 1 > row0 + 8) sacc[j][3] = -1e30f;
                    }
                }

                float rm0 = -1e30f, rm1 = -1e30f;
                #pragma unroll
                for (int j = 0; j < 8; j++) {
                    rm0 = fmaxf(rm0, fmaxf(sacc[j][0], sacc[j][1]));
                    rm1 = fmaxf(rm1, fmaxf(sacc[j][2], sacc[j][3]));
                }
                rm0 = fmaxf(rm0, __shfl_xor_sync(0xffffffffu, rm0, 1));
                rm0 = fmaxf(rm0, __shfl_xor_sync(0xffffffffu, rm0, 2));
                rm1 = fmaxf(rm1, __shfl_xor_sync(0xffffffffu, rm1, 1));
                rm1 = fmaxf(rm1, __shfl_xor_sync(0xffffffffu, rm1, 2));
                float nm0 = fmaxf(m0r, rm0), nm1 = fmaxf(m1r, rm1);
                float corr0 = exp2f((m0r - nm0) * c2);
                float corr1 = exp2f((m1r - nm1) * c2);
                m0r = nm0; m1r = nm1;
                float nc0 = nm0 * c2, nc1 = nm1 * c2;

                // p = 2^(s*c2 - nm*c2) in f16x2 — IS the PV fragment
                uint32_t ph[8][2];
                #pragma unroll
                for (int j = 0; j < 8; j++) {
                    float d0 = fmaf(sacc[j][0], c2, -nc0);
                    float d1 = fmaf(sacc[j][1], c2, -nc0);
                    float d2 = fmaf(sacc[j][2], c2, -nc1);
                    float d3 = fmaf(sacc[j][3], c2, -nc1);
                    ph[j][0] = ex2_f16x2(d0, d1);
                    ph[j][1] = ex2_f16x2(d2, d3);
                }

                // rescale O and l accumulators
                #pragma unroll
                for (int j = 0; j < 8; j++) {
                    oacc[j][0] *= corr0; oacc[j][1] *= corr0;
                    oacc[j][2] *= corr1; oacc[j][3] *= corr1;
                }
                lsum[0] *= corr0; lsum[1] *= corr0;
                lsum[2] *= corr1; lsum[3] *= corr1;

                // O += P @ V, and l += P @ ones (row-sum via MMA, no shfl)
                int mi = lane >> 3, rr = lane & 7;
                #pragma unroll
                for (int kc = 0; kc < 4; kc++) {
                    uint32_t pf[4];
                    pf[0] = ph[2 * kc][0];
                    pf[1] = ph[2 * kc][1];
                    pf[2] = ph[2 * kc + 1][0];
                    pf[3] = ph[2 * kc + 1][1];

                    mma16816(lsum, pf, ONES16, ONES16);

                    #pragma unroll
                    for (int jop = 0; jop < 4; jop++) {
                        uint32_t r0, r1, r2, r3;
                        const __half* vp = &Vs[sl][(kc * 16 + (mi & 1) * 8 + rr) * LKV
                                                   + jop * 16 + (mi >> 1) * 8];
                        uint32_t va = (uint32_t)__cvta_generic_to_shared(vp);
                        asm volatile(
                            "ldmatrix.sync.aligned.m8n8.x4.trans.shared.b16 "
                            "{%0,%1,%2,%3}, [%4];"
                            : "=r"(r0), "=r"(r1), "=r"(r2), "=r"(r3) : "r"(va));
                        mma16816(oacc[2 * jop],     pf, r0, r1);
                        mma16816(oacc[2 * jop + 1], pf, r2, r3);
                    }
                }
            }
        }

        __syncthreads();   // all warps done with smem before sub1 reuse

        float inv0 = 1.0f / lsum[0], inv1 = 1.0f / lsum[2];
        #pragma unroll
        for (int j = 0; j < 8; j++) {
            int c = j * 8 + tig * 2;
            *(__half2*)&ob[(size_t)row0 * D_ + c] =
                __floats2half2_rn(oacc[j][0] * inv0, oacc[j][1] * inv0);
            *(__half2*)&ob[(size_t)(row0 + 8) * D_ + c] =
                __floats2half2_rn(oacc[j][2] * inv1, oacc[j][3] * inv1);
        }
    }
}

// ---------------------------------------------------------------------------

extern "C" void kernel_launch(void* const* d_in, const int* in_sizes, int n_in,
                              void* d_out, int out_size)
{
    const float* x  = (const float*)d_in[0];
    const float* wq = (const float*)d_in[1];
    const float* wk = (const float*)d_in[2];
    const float* wv = (const float*)d_in[3];
    const float* wo = (const float*)d_in[4];
    float* out = (float*)d_out;

    __half *qh, *kh, *vh, *atth, *xh, *wqh, *wkh, *wvh, *woh;
    cudaGetSymbolAddress((void**)&qh,   g_qh);
    cudaGetSymbolAddress((void**)&kh,   g_kh);
    cudaGetSymbolAddress((void**)&vh,   g_vh);
    cudaGetSymbolAddress((void**)&atth, g_atth);
    cudaGetSymbolAddress((void**)&xh,   g_xh);
    cudaGetSymbolAddress((void**)&wqh,  g_wqh);
    cudaGetSymbolAddress((void**)&wkh,  g_wkh);
    cudaGetSymbolAddress((void**)&wvh,  g_wvh);
    cudaGetSymbolAddress((void**)&woh,  g_woh);

    convert_all_kernel<<<2048, 256>>>(x, wq, wk, wv, wo,
                                      xh, wqh, wkh, wvh, woh);

    cudaFuncSetAttribute(gemm_nt_f16_kernel<__half>,
                         cudaFuncAttributeMaxDynamicSharedMemorySize, GSM3);
    cudaFuncSetAttribute(gemm_nt_f16_kernel<float>,
                         cudaFuncAttributeMaxDynamicSharedMemorySize, GSM3);

    cudaLaunchAttribute pdl[1];
    pdl[0].id = cudaLaunchAttributeProgrammaticStreamSerialization;
    pdl[0].val.programmaticStreamSerializationAllowed = 1;

    // Fused QKV projection (PDL after convert)
    {
        cudaLaunchConfig_t cfg = {};
        cfg.gridDim  = dim3(D_ / 128, NT_ / 128, 3);
        cfg.blockDim = dim3(256, 1, 1);
        cfg.dynamicSmemBytes = GSM3;
        cfg.attrs = pdl; cfg.numAttrs = 1;
        cudaLaunchKernelEx(&cfg, gemm_nt_f16_kernel<__half>,
                           (const __half*)xh,
                           (const __half*)wqh, (const __half*)wkh,
                           (const __half*)wvh,
                           qh, kh, vh, (int)NT_, (int)D_, (int)D_);
    }

    // Paired attention (PDL after QKV)
    {
        cudaLaunchConfig_t cfg = {};
        cfg.gridDim  = dim3(NQT / 2, H_, B_);
        cfg.blockDim = dim3(256, 1, 1);
        cfg.dynamicSmemBytes = 0;
        cfg.attrs = pdl; cfg.numAttrs = 1;
        cudaLaunchKernelEx(&cfg, attn_f16_kernel,
                           (const __half*)qh, (const __half*)kh,
                           (const __half*)vh, atth);
    }

    // Output projection (PDL after attention)
    {
        cudaLaunchConfig_t cfg = {};
        cfg.gridDim  = dim3(D_ / 128, NT_ / 128, 1);
        cfg.blockDim = dim3(256, 1, 1);
        cfg.dynamicSmemBytes = GSM3;
        cfg.attrs = pdl; cfg.numAttrs = 1;
        cudaLaunchKernelEx(&cfg, gemm_nt_f16_kernel<float>,
                           (const __half*)atth,
                           (const __half*)woh, (const __half*)woh,
                           (const __half*)woh,
                           out, out, out, (int)NT_, (int)D_, (int)D_);
    }
}